// round 7
// baseline (speedup 1.0000x reference)
#include <cuda_runtime.h>
#include <cuda_bf16.h>
#include <math_constants.h>
#include <cstdint>

// Attention B=256,H=16,Nq=Nk=49,D=64 fp32. One CTA (256 thr, 8 warps) per (b,h).
// Split-K: warp (m = w&3, s = w>>2) computes q-tile m (16 rows) x k-half s (32 cols).
// bf16 hi/lo 3-term tensor-core GEMMs. Q streamed gmem->regs (2-deep pipeline).
// Cross-warp softmax stats + O-partial reduction via smem (K buffers reused).
// __launch_bounds__(256,4) => <=64 regs => 32 warps/SM.

namespace {
constexpr int kNQ = 49, kNK = 49, kD = 64;
constexpr int kP  = 72;                 // bf16 pitch (144B, odd multiple of 16B)
constexpr float kScale = 0.125f;
constexpr float kEps   = 1e-9f;
constexpr int OPELEMS = 64 * kP;        // 4608 bf16 per operand array
constexpr int kOP = 34;                 // sO fp32 pitch (per 32-col half)
constexpr int kOWORDS = 4 * 16 * kOP;   // 2176 words per half region
}

__device__ __forceinline__ uint32_t cvta_s(const void* p) {
    return (uint32_t)__cvta_generic_to_shared(p);
}
__device__ __forceinline__ void ldsm4(uint32_t& r0, uint32_t& r1, uint32_t& r2, uint32_t& r3, uint32_t a) {
    asm volatile("ldmatrix.sync.aligned.m8n8.x4.shared.b16 {%0,%1,%2,%3}, [%4];\n"
                 : "=r"(r0), "=r"(r1), "=r"(r2), "=r"(r3) : "r"(a));
}
__device__ __forceinline__ void ldsm4t(uint32_t& r0, uint32_t& r1, uint32_t& r2, uint32_t& r3, uint32_t a) {
    asm volatile("ldmatrix.sync.aligned.m8n8.x4.trans.shared.b16 {%0,%1,%2,%3}, [%4];\n"
                 : "=r"(r0), "=r"(r1), "=r"(r2), "=r"(r3) : "r"(a));
}
__device__ __forceinline__ void mma16816(float* c,
                                         uint32_t a0, uint32_t a1, uint32_t a2, uint32_t a3,
                                         uint32_t b0, uint32_t b1) {
    asm volatile("mma.sync.aligned.m16n8k16.row.col.f32.bf16.bf16.f32 "
                 "{%0,%1,%2,%3}, {%4,%5,%6,%7}, {%8,%9}, {%0,%1,%2,%3};\n"
                 : "+f"(c[0]), "+f"(c[1]), "+f"(c[2]), "+f"(c[3])
                 : "r"(a0), "r"(a1), "r"(a2), "r"(a3), "r"(b0), "r"(b1));
}
__device__ __forceinline__ uint32_t packbf2(float lo, float hi) {
    uint32_t r;
    asm("cvt.rn.bf16x2.f32 %0, %1, %2;" : "=r"(r) : "f"(hi), "f"(lo));
    return r;
}
__device__ __forceinline__ float2 unpackbf2(uint32_t h) {
    return make_float2(__uint_as_float(h << 16), __uint_as_float(h & 0xffff0000u));
}

__global__ __launch_bounds__(256, 4)
void attn49_sk(const float* __restrict__ gq,
               const float* __restrict__ gk,
               const float* __restrict__ gv,
               float* __restrict__ gout)
{
    __shared__ __align__(16) char sraw[4 * OPELEMS * 2 + 2 * 2 * 64 * 4];
    __nv_bfloat16* sKh = (__nv_bfloat16*)sraw;            // [0, 9216)
    __nv_bfloat16* sKl = sKh + OPELEMS;                   // [9216, 18432)
    __nv_bfloat16* sVh = sKl + OPELEMS;                   // [18432, 27648)
    __nv_bfloat16* sVl = sVh + OPELEMS;                   // [27648, 36864)
    float* sMax = (float*)(sraw + 4 * OPELEMS * 2);       // [2][64]
    float* sSum = sMax + 128;                             // [2][64]
    float* sO   = (float*)sraw;                           // overlays K (dead after phase1)

    const int tid  = threadIdx.x;
    const int w    = tid >> 5;
    const int lane = tid & 31;
    const int g    = lane >> 3;
    const int lr   = lane & 7;
    const int m    = w & 3;        // q-tile
    const int s    = w >> 2;       // k-half
    const int kb   = s * 32;       // this warp's k-col base

    const size_t base = (size_t)blockIdx.x * (kNQ * kD);
    const float2* Q2 = (const float2*)(gq + base);
    const float2* K2 = (const float2*)(gk + base);
    const float2* V2 = (const float2*)(gv + base);
    float* O = gout + base;

    const int qtb = m * 16;
    const int q0 = qtb + (lane >> 2);
    const int q1 = q0 + 8;
    const bool p0 = q0 < kNQ;
    const bool p1 = q1 < kNQ;
    const int cq = 2 * (lane & 3);

    // ---- Q fragment gmem loads: 2-deep pipeline buffers (fp32) ----
    float2 qf[2][4];
    {
        const int cb = lane & 3;   // kc=0
        qf[0][0] = p0 ? Q2[q0 * 32 + cb]     : make_float2(0.f, 0.f);
        qf[0][1] = p1 ? Q2[q1 * 32 + cb]     : make_float2(0.f, 0.f);
        qf[0][2] = p0 ? Q2[q0 * 32 + cb + 4] : make_float2(0.f, 0.f);
        qf[0][3] = p1 ? Q2[q1 * 32 + cb + 4] : make_float2(0.f, 0.f);
    }

    // ---- Cooperative K,V load + hi/lo split (256 threads) ----
    uint32_t* Kh2 = (uint32_t*)sKh;
    uint32_t* Kl2 = (uint32_t*)sKl;
    uint32_t* Vh2 = (uint32_t*)sVh;
    uint32_t* Vl2 = (uint32_t*)sVl;
    for (int idx = tid; idx < (kNK * kD) / 2; idx += 256) {
        const int r = idx >> 5, c2 = idx & 31;
        const float2 k = K2[idx];
        const float2 v = V2[idx];
        const uint32_t kh = packbf2(k.x, k.y);
        const uint32_t vh = packbf2(v.x, v.y);
        const float2 kf = unpackbf2(kh);
        const float2 vf = unpackbf2(vh);
        Kh2[r * 36 + c2] = kh;
        Kl2[r * 36 + c2] = packbf2(k.x - kf.x, k.y - kf.y);
        Vh2[r * 36 + c2] = vh;
        Vl2[r * 36 + c2] = packbf2(v.x - vf.x, v.y - vf.y);
    }
    for (int i = tid; i < 15 * 36; i += 256) {
        const int off = (kNK + i / 36) * 36 + (i % 36);
        Vh2[off] = 0u; Vl2[off] = 0u;     // V pads zero; K pads masked downstream
    }
    __syncthreads();   // bar 1: K,V visible

    // ---- Phase 1: S[16q][32k] for this warp's k-half ----
    float acc[4][4];
    #pragma unroll
    for (int i = 0; i < 4; i++)
        #pragma unroll
        for (int j = 0; j < 4; j++) acc[i][j] = 0.0f;
    {
        const uint32_t aKh = cvta_s(sKh), aKl = cvta_s(sKl);
        #pragma unroll
        for (int kc = 0; kc < 4; kc++) {
            // prefetch next Q chunk
            if (kc < 3) {
                const int cb = (kc + 1) * 8 + (lane & 3);
                float2* nb = qf[(kc + 1) & 1];
                nb[0] = p0 ? Q2[q0 * 32 + cb]     : make_float2(0.f, 0.f);
                nb[1] = p1 ? Q2[q1 * 32 + cb]     : make_float2(0.f, 0.f);
                nb[2] = p0 ? Q2[q0 * 32 + cb + 4] : make_float2(0.f, 0.f);
                nb[3] = p1 ? Q2[q1 * 32 + cb + 4] : make_float2(0.f, 0.f);
            }
            // convert current chunk (scale + hi/lo split)
            uint32_t ah[4], al[4];
            #pragma unroll
            for (int j = 0; j < 4; j++) {
                float2 x = qf[kc & 1][j];
                x.x *= kScale; x.y *= kScale;
                const uint32_t h = packbf2(x.x, x.y);
                const float2 f = unpackbf2(h);
                ah[j] = h;
                al[j] = packbf2(x.x - f.x, x.y - f.y);
            }
            const int d = kc * 16;
            #pragma unroll
            for (int nt2 = 0; nt2 < 2; nt2++) {
                const int bo = (kb + nt2 * 16 + lr + ((g & 1) << 3)) * kP + d + ((g >> 1) << 3);
                uint32_t bh0, bh1, bh2, bh3, bl0, bl1, bl2, bl3;
                ldsm4(bh0, bh1, bh2, bh3, aKh + bo * 2);
                ldsm4(bl0, bl1, bl2, bl3, aKl + bo * 2);
                mma16816(acc[2 * nt2], ah[0], ah[1], ah[2], ah[3], bh0, bh2);
                mma16816(acc[2 * nt2], ah[0], ah[1], ah[2], ah[3], bl0, bl2);
                mma16816(acc[2 * nt2], al[0], al[1], al[2], al[3], bh0, bh2);
                if (s == 0 || nt2 == 0) {     // skip all-invalid n-tile (k 56-63)
                    mma16816(acc[2 * nt2 + 1], ah[0], ah[1], ah[2], ah[3], bh1, bh3);
                    mma16816(acc[2 * nt2 + 1], ah[0], ah[1], ah[2], ah[3], bl1, bl3);
                    mma16816(acc[2 * nt2 + 1], al[0], al[1], al[2], al[3], bh1, bh3);
                }
            }
        }
    }

    // ---- Softmax: partial max over this k-half (quad shuffles), exchange ----
    float m0 = -CUDART_INF_F, m1 = -CUDART_INF_F;
    #pragma unroll
    for (int nt = 0; nt < 4; nt++) {
        const int c0 = kb + nt * 8 + cq;
        const bool v0 = (c0 < kNK), v1 = (c0 + 1 < kNK);
        m0 = fmaxf(m0, v0 ? acc[nt][0] : -CUDART_INF_F);
        m0 = fmaxf(m0, v1 ? acc[nt][1] : -CUDART_INF_F);
        m1 = fmaxf(m1, v0 ? acc[nt][2] : -CUDART_INF_F);
        m1 = fmaxf(m1, v1 ? acc[nt][3] : -CUDART_INF_F);
    }
    m0 = fmaxf(m0, __shfl_xor_sync(0xffffffffu, m0, 1));
    m0 = fmaxf(m0, __shfl_xor_sync(0xffffffffu, m0, 2));
    m1 = fmaxf(m1, __shfl_xor_sync(0xffffffffu, m1, 1));
    m1 = fmaxf(m1, __shfl_xor_sync(0xffffffffu, m1, 2));
    if ((lane & 3) == 0) {
        sMax[s * 64 + q0] = m0;
        sMax[s * 64 + q1] = m1;
    }
    __syncthreads();   // bar 2: max partials (also: K smem free after this)
    m0 = fmaxf(sMax[q0], sMax[64 + q0]);
    m1 = fmaxf(sMax[q1], sMax[64 + q1]);

    float l0 = 0.0f, l1 = 0.0f;
    #pragma unroll
    for (int nt = 0; nt < 4; nt++) {
        const int c0 = kb + nt * 8 + cq;
        const bool v0 = (c0 < kNK), v1 = (c0 + 1 < kNK);
        const float e0 = v0 ? __expf(acc[nt][0] - m0) : 0.0f;
        const float e1 = v1 ? __expf(acc[nt][1] - m0) : 0.0f;
        const float e2 = v0 ? __expf(acc[nt][2] - m1) : 0.0f;
        const float e3 = v1 ? __expf(acc[nt][3] - m1) : 0.0f;
        acc[nt][0] = e0; acc[nt][1] = e1; acc[nt][2] = e2; acc[nt][3] = e3;
        l0 += e0 + e1; l1 += e2 + e3;
    }
    l0 += __shfl_xor_sync(0xffffffffu, l0, 1);
    l0 += __shfl_xor_sync(0xffffffffu, l0, 2);
    l1 += __shfl_xor_sync(0xffffffffu, l1, 1);
    l1 += __shfl_xor_sync(0xffffffffu, l1, 2);
    if ((lane & 3) == 0) {
        sSum[s * 64 + q0] = l0;
        sSum[s * 64 + q1] = l1;
    }
    __syncthreads();   // bar 3: sum partials
    const float linv0 = 1.0f / (sSum[q0] + sSum[64 + q0] + kEps);
    const float linv1 = 1.0f / (sSum[q1] + sSum[64 + q1] + kEps);

    // ---- Repack P fragments (this k-half: 2 kc chunks) ----
    uint32_t aH[2][4], aL[2][4];
    #pragma unroll
    for (int kc2 = 0; kc2 < 2; kc2++) {
        #pragma unroll
        for (int t = 0; t < 2; t++) {
            const float e0 = acc[2 * kc2 + t][0], e1 = acc[2 * kc2 + t][1];
            const float e2 = acc[2 * kc2 + t][2], e3 = acc[2 * kc2 + t][3];
            const uint32_t h01 = packbf2(e0, e1);
            const uint32_t h23 = packbf2(e2, e3);
            const float2 f01 = unpackbf2(h01);
            const float2 f23 = unpackbf2(h23);
            aH[kc2][2 * t]     = h01;
            aH[kc2][2 * t + 1] = h23;
            aL[kc2][2 * t]     = packbf2(e0 - f01.x, e1 - f01.y);
            aL[kc2][2 * t + 1] = packbf2(e2 - f23.x, e3 - f23.y);
        }
    }

    // ---- Phase 2: O partial over this k-half; reduce pairs through smem ----
    const uint32_t aVh = cvta_s(sVh), aVl = cvta_s(sVl);
    const int rl = lane >> 2;      // local row 0..7 (and +8)
    #pragma unroll
    for (int half = 0; half < 2; half++) {
        const int db = half * 32;
        float o[4][4];
        #pragma unroll
        for (int i = 0; i < 4; i++)
            #pragma unroll
            for (int j = 0; j < 4; j++) o[i][j] = 0.0f;

        #pragma unroll
        for (int kc2 = 0; kc2 < 2; kc2++) {
            const int kk = kb + kc2 * 16;
            #pragma unroll
            for (int nt2 = 0; nt2 < 2; nt2++) {
                const int bo = (kk + ((g >> 1) << 3) + lr) * kP + db + nt2 * 16 + ((g & 1) << 3);
                uint32_t bh0, bh1, bh2, bh3, bl0, bl1, bl2, bl3;
                ldsm4t(bh0, bh1, bh2, bh3, aVh + bo * 2);
                ldsm4t(bl0, bl1, bl2, bl3, aVl + bo * 2);
                mma16816(o[2 * nt2],     aH[kc2][0], aH[kc2][1], aH[kc2][2], aH[kc2][3], bh0, bh2);
                mma16816(o[2 * nt2 + 1], aH[kc2][0], aH[kc2][1], aH[kc2][2], aH[kc2][3], bh1, bh3);
                mma16816(o[2 * nt2],     aH[kc2][0], aH[kc2][1], aH[kc2][2], aH[kc2][3], bl0, bl2);
                mma16816(o[2 * nt2 + 1], aH[kc2][0], aH[kc2][1], aH[kc2][2], aH[kc2][3], bl1, bl3);
                mma16816(o[2 * nt2],     aL[kc2][0], aL[kc2][1], aL[kc2][2], aL[kc2][3], bh0, bh2);
                mma16816(o[2 * nt2 + 1], aL[kc2][0], aL[kc2][1], aL[kc2][2], aL[kc2][3], bh1, bh3);
            }
        }

        float* sOh = sO + half * kOWORDS;
        if (s == 0) {
            #pragma unroll
            for (int nt = 0; nt < 4; nt++) {
                const int col = nt * 8 + cq;
                *(float2*)&sOh[(m * 16 + rl) * kOP + col]       = make_float2(o[nt][0], o[nt][1]);
                *(float2*)&sOh[(m * 16 + rl + 8) * kOP + col]   = make_float2(o[nt][2], o[nt][3]);
            }
        }
        __syncthreads();   // bar 4/5: half's partials visible
        if (s == 1) {
            #pragma unroll
            for (int nt = 0; nt < 4; nt++) {
                const int col = nt * 8 + cq;
                const float2 a0 = *(const float2*)&sOh[(m * 16 + rl) * kOP + col];
                const float2 a1 = *(const float2*)&sOh[(m * 16 + rl + 8) * kOP + col];
                const int d = db + col;
                if (p0)
                    *(float2*)(O + q0 * kD + d) =
                        make_float2((o[nt][0] + a0.x) * linv0, (o[nt][1] + a0.y) * linv0);
                if (p1)
                    *(float2*)(O + q1 * kD + d) =
                        make_float2((o[nt][2] + a1.x) * linv1, (o[nt][3] + a1.y) * linv1);
            }
        }
    }
}

extern "C" void kernel_launch(void* const* d_in, const int* in_sizes, int n_in,
                              void* d_out, int out_size)
{
    const float* q = (const float*)d_in[0];
    const float* k = (const float*)d_in[1];
    const float* v = (const float*)d_in[2];
    float* out = (float*)d_out;

    const int bh = in_sizes[0] / (kNQ * kD);   // 4096
    attn49_sk<<<bh, 256>>>(q, k, v, out);
}

// round 8
// speedup vs baseline: 1.1083x; 1.1083x over previous
#include <cuda_runtime.h>
#include <cuda_bf16.h>
#include <math_constants.h>
#include <cstdint>

// Attention B=256,H=16,Nq=Nk=49,D=64 fp32. One CTA (128 thr, 4 warps) per (b,h).
// bf16 hi/lo 3-term tensor-core GEMMs; warp w owns q rows [16w,16w+16).
// Q streamed gmem->regs with a 2-deep fp32 pipeline (no Q smem).
// K hi/lo stored with only 49 rows (LDSM pad-row reads spill into adjacent
// arrays; values are softmax-masked) -> smem 31.8KB; launch_bounds(128,7)
// => 7 CTAs/SM (28 warps). One __syncthreads(). Softmax+P fully in registers.

namespace {
constexpr int kNQ = 49, kNK = 49, kD = 64;
constexpr int kP  = 72;                  // bf16 pitch (144B = 9*16, odd multiple of 16B)
constexpr float kScale = 0.125f;
constexpr float kEps   = 1e-9f;
constexpr int kKBYTES = 49 * kP * 2;     // 7056  (49 rows only; reads may spill)
constexpr int kVBYTES = 64 * kP * 2;     // 9216  (64 rows, pads zeroed)
constexpr int OFF_KH = 0;
constexpr int OFF_KL = OFF_KH + kKBYTES;         // 7056
constexpr int OFF_VH = OFF_KL + kKBYTES;         // 14112
constexpr int OFF_VL = OFF_VH + kVBYTES;         // 23328
constexpr int SMEM_BYTES = OFF_VL + kVBYTES;     // 32544
}

__device__ __forceinline__ uint32_t cvta_s(const void* p) {
    return (uint32_t)__cvta_generic_to_shared(p);
}
__device__ __forceinline__ void ldsm4(uint32_t& r0, uint32_t& r1, uint32_t& r2, uint32_t& r3, uint32_t a) {
    asm volatile("ldmatrix.sync.aligned.m8n8.x4.shared.b16 {%0,%1,%2,%3}, [%4];\n"
                 : "=r"(r0), "=r"(r1), "=r"(r2), "=r"(r3) : "r"(a));
}
__device__ __forceinline__ void ldsm4t(uint32_t& r0, uint32_t& r1, uint32_t& r2, uint32_t& r3, uint32_t a) {
    asm volatile("ldmatrix.sync.aligned.m8n8.x4.trans.shared.b16 {%0,%1,%2,%3}, [%4];\n"
                 : "=r"(r0), "=r"(r1), "=r"(r2), "=r"(r3) : "r"(a));
}
__device__ __forceinline__ void mma16816(float* c,
                                         uint32_t a0, uint32_t a1, uint32_t a2, uint32_t a3,
                                         uint32_t b0, uint32_t b1) {
    asm volatile("mma.sync.aligned.m16n8k16.row.col.f32.bf16.bf16.f32 "
                 "{%0,%1,%2,%3}, {%4,%5,%6,%7}, {%8,%9}, {%0,%1,%2,%3};\n"
                 : "+f"(c[0]), "+f"(c[1]), "+f"(c[2]), "+f"(c[3])
                 : "r"(a0), "r"(a1), "r"(a2), "r"(a3), "r"(b0), "r"(b1));
}
__device__ __forceinline__ uint32_t packbf2(float lo, float hi) {
    uint32_t r;
    asm("cvt.rn.bf16x2.f32 %0, %1, %2;" : "=r"(r) : "f"(hi), "f"(lo));
    return r;
}
__device__ __forceinline__ float2 unpackbf2(uint32_t h) {
    return make_float2(__uint_as_float(h << 16), __uint_as_float(h & 0xffff0000u));
}

__global__ __launch_bounds__(128, 7)
void attn49_v8(const float* __restrict__ gq,
               const float* __restrict__ gk,
               const float* __restrict__ gv,
               float* __restrict__ gout)
{
    __shared__ __align__(16) char sraw[SMEM_BYTES];
    uint32_t* Kh2 = (uint32_t*)(sraw + OFF_KH);
    uint32_t* Kl2 = (uint32_t*)(sraw + OFF_KL);
    uint32_t* Vh2 = (uint32_t*)(sraw + OFF_VH);
    uint32_t* Vl2 = (uint32_t*)(sraw + OFF_VL);

    const int tid  = threadIdx.x;
    const int w    = tid >> 5;
    const int lane = tid & 31;
    const int g    = lane >> 3;
    const int lr   = lane & 7;

    const size_t base = (size_t)blockIdx.x * (kNQ * kD);
    const float2* Q2 = (const float2*)(gq + base);
    const float2* K2 = (const float2*)(gk + base);
    const float2* V2 = (const float2*)(gv + base);
    float* O = gout + base;

    const int qtb = w * 16;
    const int q0 = qtb + (lane >> 2);
    const int q1 = q0 + 8;
    const bool p0 = q0 < kNQ;
    const bool p1 = q1 < kNQ;
    const int cq = 2 * (lane & 3);

    // ---- Q pipeline: preload kc=0 chunk (fp32) so latency overlaps K/V phase ----
    float2 qf[2][4];
    {
        const int cb = lane & 3;
        qf[0][0] = p0 ? Q2[q0 * 32 + cb]     : make_float2(0.f, 0.f);
        qf[0][1] = p1 ? Q2[q1 * 32 + cb]     : make_float2(0.f, 0.f);
        qf[0][2] = p0 ? Q2[q0 * 32 + cb + 4] : make_float2(0.f, 0.f);
        qf[0][3] = p1 ? Q2[q1 * 32 + cb + 4] : make_float2(0.f, 0.f);
    }

    // ---- Cooperative K,V load + hi/lo split ----
    for (int idx = tid; idx < (kNK * kD) / 2; idx += 128) {
        const int r = idx >> 5, c2 = idx & 31;
        const float2 k = K2[idx];
        const float2 v = V2[idx];
        const uint32_t kh = packbf2(k.x, k.y);
        const uint32_t vh = packbf2(v.x, v.y);
        const float2 kf = unpackbf2(kh);
        const float2 vf = unpackbf2(vh);
        Kh2[r * 36 + c2] = kh;                              // rows 0..48 only
        Kl2[r * 36 + c2] = packbf2(k.x - kf.x, k.y - kf.y);
        Vh2[r * 36 + c2] = vh;
        Vl2[r * 36 + c2] = packbf2(v.x - vf.x, v.y - vf.y);
    }
    // V pad rows 49..63 zero (P cols k>=49 are exact zeros; avoid NaN*0)
    for (int i = tid; i < 15 * 36; i += 128) {
        const int off = (kNK + i / 36) * 36 + (i % 36);
        Vh2[off] = 0u; Vl2[off] = 0u;
    }
    __syncthreads();   // the ONLY barrier

    // ---- Phase 1: S[16q][64k] ----
    float acc[8][4];
    #pragma unroll
    for (int i = 0; i < 8; i++)
        #pragma unroll
        for (int j = 0; j < 4; j++) acc[i][j] = 0.0f;
    {
        const uint32_t aKh = cvta_s(sraw + OFF_KH);
        const uint32_t aKl = cvta_s(sraw + OFF_KL);
        #pragma unroll
        for (int kc = 0; kc < 4; kc++) {
            if (kc < 3) {    // prefetch next Q chunk
                const int cb = (kc + 1) * 8 + (lane & 3);
                float2* nb = qf[(kc + 1) & 1];
                nb[0] = p0 ? Q2[q0 * 32 + cb]     : make_float2(0.f, 0.f);
                nb[1] = p1 ? Q2[q1 * 32 + cb]     : make_float2(0.f, 0.f);
                nb[2] = p0 ? Q2[q0 * 32 + cb + 4] : make_float2(0.f, 0.f);
                nb[3] = p1 ? Q2[q1 * 32 + cb + 4] : make_float2(0.f, 0.f);
            }
            uint32_t ah[4], al[4];
            #pragma unroll
            for (int j = 0; j < 4; j++) {
                float2 x = qf[kc & 1][j];
                x.x *= kScale; x.y *= kScale;
                const uint32_t h = packbf2(x.x, x.y);
                const float2 f = unpackbf2(h);
                ah[j] = h;
                al[j] = packbf2(x.x - f.x, x.y - f.y);
            }
            const int d = kc * 16;
            #pragma unroll
            for (int nt2 = 0; nt2 < 4; nt2++) {
                const int bo = (nt2 * 16 + lr + ((g & 1) << 3)) * kP + d + ((g >> 1) << 3);
                uint32_t bh0, bh1, bh2, bh3, bl0, bl1, bl2, bl3;
                ldsm4(bh0, bh1, bh2, bh3, aKh + bo * 2);   // rows >48 spill: masked later
                ldsm4(bl0, bl1, bl2, bl3, aKl + bo * 2);
                mma16816(acc[2 * nt2],     ah[0], ah[1], ah[2], ah[3], bh0, bh2);
                mma16816(acc[2 * nt2 + 1], ah[0], ah[1], ah[2], ah[3], bh1, bh3);
                mma16816(acc[2 * nt2],     ah[0], ah[1], ah[2], ah[3], bl0, bl2);
                mma16816(acc[2 * nt2 + 1], ah[0], ah[1], ah[2], ah[3], bl1, bl3);
                mma16816(acc[2 * nt2],     al[0], al[1], al[2], al[3], bh0, bh2);
                mma16816(acc[2 * nt2 + 1], al[0], al[1], al[2], al[3], bh1, bh3);
            }
        }
    }

    // ---- Register softmax (rows q0: acc[..][0,1]; q1: acc[..][2,3]) ----
    float m0 = -CUDART_INF_F, m1 = -CUDART_INF_F;
    #pragma unroll
    for (int nt = 0; nt < 8; nt++) {
        const int c0 = nt * 8 + cq;
        const bool v0 = (c0 < kNK), v1 = (c0 + 1 < kNK);
        m0 = fmaxf(m0, v0 ? acc[nt][0] : -CUDART_INF_F);
        m0 = fmaxf(m0, v1 ? acc[nt][1] : -CUDART_INF_F);
        m1 = fmaxf(m1, v0 ? acc[nt][2] : -CUDART_INF_F);
        m1 = fmaxf(m1, v1 ? acc[nt][3] : -CUDART_INF_F);
    }
    m0 = fmaxf(m0, __shfl_xor_sync(0xffffffffu, m0, 1));
    m0 = fmaxf(m0, __shfl_xor_sync(0xffffffffu, m0, 2));
    m1 = fmaxf(m1, __shfl_xor_sync(0xffffffffu, m1, 1));
    m1 = fmaxf(m1, __shfl_xor_sync(0xffffffffu, m1, 2));

    float l0 = 0.0f, l1 = 0.0f;
    #pragma unroll
    for (int nt = 0; nt < 8; nt++) {
        const int c0 = nt * 8 + cq;
        const bool v0 = (c0 < kNK), v1 = (c0 + 1 < kNK);
        const float e0 = v0 ? __expf(acc[nt][0] - m0) : 0.0f;
        const float e1 = v1 ? __expf(acc[nt][1] - m0) : 0.0f;
        const float e2 = v0 ? __expf(acc[nt][2] - m1) : 0.0f;
        const float e3 = v1 ? __expf(acc[nt][3] - m1) : 0.0f;
        acc[nt][0] = e0; acc[nt][1] = e1; acc[nt][2] = e2; acc[nt][3] = e3;
        l0 += e0 + e1; l1 += e2 + e3;
    }
    l0 += __shfl_xor_sync(0xffffffffu, l0, 1);
    l0 += __shfl_xor_sync(0xffffffffu, l0, 2);
    l1 += __shfl_xor_sync(0xffffffffu, l1, 1);
    l1 += __shfl_xor_sync(0xffffffffu, l1, 2);
    const float linv0 = 1.0f / (l0 + kEps);
    const float linv1 = 1.0f / (l1 + kEps);

    // ---- Repack S C-fragments as A-fragments (m16k16) hi/lo, in registers ----
    uint32_t aH[4][4], aL[4][4];
    #pragma unroll
    for (int kc = 0; kc < 4; kc++) {
        #pragma unroll
        for (int t = 0; t < 2; t++) {
            const float e0 = acc[2 * kc + t][0], e1 = acc[2 * kc + t][1];
            const float e2 = acc[2 * kc + t][2], e3 = acc[2 * kc + t][3];
            const uint32_t h01 = packbf2(e0, e1);
            const uint32_t h23 = packbf2(e2, e3);
            const float2 f01 = unpackbf2(h01);
            const float2 f23 = unpackbf2(h23);
            aH[kc][2 * t]     = h01;
            aH[kc][2 * t + 1] = h23;
            aL[kc][2 * t]     = packbf2(e0 - f01.x, e1 - f01.y);
            aL[kc][2 * t + 1] = packbf2(e2 - f23.x, e3 - f23.y);
        }
    }

    // ---- Phase 2: O = P.V ----
    const uint32_t aVh = cvta_s(sraw + OFF_VH);
    const uint32_t aVl = cvta_s(sraw + OFF_VL);
    #pragma unroll
    for (int half = 0; half < 2; half++) {
        const int db = half * 32;
        float o[4][4];
        #pragma unroll
        for (int i = 0; i < 4; i++)
            #pragma unroll
            for (int j = 0; j < 4; j++) o[i][j] = 0.0f;

        #pragma unroll
        for (int kc = 0; kc < 4; kc++) {
            const int kk = kc * 16;
            #pragma unroll
            for (int nt2 = 0; nt2 < 2; nt2++) {
                const int bo = (kk + ((g >> 1) << 3) + lr) * kP + db + nt2 * 16 + ((g & 1) << 3);
                uint32_t bh0, bh1, bh2, bh3, bl0, bl1, bl2, bl3;
                ldsm4t(bh0, bh1, bh2, bh3, aVh + bo * 2);
                ldsm4t(bl0, bl1, bl2, bl3, aVl + bo * 2);
                mma16816(o[2 * nt2],     aH[kc][0], aH[kc][1], aH[kc][2], aH[kc][3], bh0, bh2);
                mma16816(o[2 * nt2 + 1], aH[kc][0], aH[kc][1], aH[kc][2], aH[kc][3], bh1, bh3);
                mma16816(o[2 * nt2],     aH[kc][0], aH[kc][1], aH[kc][2], aH[kc][3], bl0, bl2);
                mma16816(o[2 * nt2 + 1], aH[kc][0], aH[kc][1], aH[kc][2], aH[kc][3], bl1, bl3);
                mma16816(o[2 * nt2],     aL[kc][0], aL[kc][1], aL[kc][2], aL[kc][3], bh0, bh2);
                mma16816(o[2 * nt2 + 1], aL[kc][0], aL[kc][1], aL[kc][2], aL[kc][3], bh1, bh3);
            }
        }

        #pragma unroll
        for (int nt = 0; nt < 4; nt++) {
            const int d = db + nt * 8 + cq;
            if (p0)
                *(float2*)(O + q0 * kD + d) = make_float2(o[nt][0] * linv0, o[nt][1] * linv0);
            if (p1)
                *(float2*)(O + q1 * kD + d) = make_float2(o[nt][2] * linv1, o[nt][3] * linv1);
        }
    }
}

extern "C" void kernel_launch(void* const* d_in, const int* in_sizes, int n_in,
                              void* d_out, int out_size)
{
    const float* q = (const float*)d_in[0];
    const float* k = (const float*)d_in[1];
    const float* v = (const float*)d_in[2];
    float* out = (float*)d_out;

    const int bh = in_sizes[0] / (kNQ * kD);   // 4096
    attn49_v8<<<bh, 128>>>(q, k, v, out);
}

// round 9
// speedup vs baseline: 1.1559x; 1.0430x over previous
#include <cuda_runtime.h>
#include <cuda_bf16.h>
#include <math_constants.h>
#include <cstdint>

// Attention B=256,H=16,Nq=Nk=49,D=64 fp32. One CTA (128 thr, 4 warps) per (b,h).
// bf16 hi/lo 3-term tensor-core GEMMs; warp w owns q rows [16w,16w+16).
// R9: MMAs issued over 4 independent accumulator chains (two n-tiles held
// live) so same-acc RAW spacing is 4 issues instead of 2; dead n-tile
// (k 56-63) MMAs skipped in phase 1. Q streamed gmem->regs. One barrier.

namespace {
constexpr int kNQ = 49, kNK = 49, kD = 64;
constexpr int kP  = 72;                  // bf16 pitch (144B = 9*16)
constexpr float kScale = 0.125f;
constexpr float kEps   = 1e-9f;
constexpr int kKBYTES = 49 * kP * 2;     // 7056 (49 rows; LDSM spill rows masked)
constexpr int kVBYTES = 64 * kP * 2;     // 9216 (pads zeroed)
constexpr int OFF_KH = 0;
constexpr int OFF_KL = OFF_KH + kKBYTES;
constexpr int OFF_VH = OFF_KL + kKBYTES;
constexpr int OFF_VL = OFF_VH + kVBYTES;
constexpr int SMEM_BYTES = OFF_VL + kVBYTES;   // 32544
}

__device__ __forceinline__ uint32_t cvta_s(const void* p) {
    return (uint32_t)__cvta_generic_to_shared(p);
}
__device__ __forceinline__ void ldsm4(uint32_t& r0, uint32_t& r1, uint32_t& r2, uint32_t& r3, uint32_t a) {
    asm volatile("ldmatrix.sync.aligned.m8n8.x4.shared.b16 {%0,%1,%2,%3}, [%4];\n"
                 : "=r"(r0), "=r"(r1), "=r"(r2), "=r"(r3) : "r"(a));
}
__device__ __forceinline__ void ldsm4t(uint32_t& r0, uint32_t& r1, uint32_t& r2, uint32_t& r3, uint32_t a) {
    asm volatile("ldmatrix.sync.aligned.m8n8.x4.trans.shared.b16 {%0,%1,%2,%3}, [%4];\n"
                 : "=r"(r0), "=r"(r1), "=r"(r2), "=r"(r3) : "r"(a));
}
__device__ __forceinline__ void mma16816(float* c,
                                         uint32_t a0, uint32_t a1, uint32_t a2, uint32_t a3,
                                         uint32_t b0, uint32_t b1) {
    asm volatile("mma.sync.aligned.m16n8k16.row.col.f32.bf16.bf16.f32 "
                 "{%0,%1,%2,%3}, {%4,%5,%6,%7}, {%8,%9}, {%0,%1,%2,%3};\n"
                 : "+f"(c[0]), "+f"(c[1]), "+f"(c[2]), "+f"(c[3])
                 : "r"(a0), "r"(a1), "r"(a2), "r"(a3), "r"(b0), "r"(b1));
}
__device__ __forceinline__ uint32_t packbf2(float lo, float hi) {
    uint32_t r;
    asm("cvt.rn.bf16x2.f32 %0, %1, %2;" : "=r"(r) : "f"(hi), "f"(lo));
    return r;
}
__device__ __forceinline__ float2 unpackbf2(uint32_t h) {
    return make_float2(__uint_as_float(h << 16), __uint_as_float(h & 0xffff0000u));
}

__global__ __launch_bounds__(128, 6)
void attn49_v9(const float* __restrict__ gq,
               const float* __restrict__ gk,
               const float* __restrict__ gv,
               float* __restrict__ gout)
{
    __shared__ __align__(16) char sraw[SMEM_BYTES];
    uint32_t* Kh2 = (uint32_t*)(sraw + OFF_KH);
    uint32_t* Kl2 = (uint32_t*)(sraw + OFF_KL);
    uint32_t* Vh2 = (uint32_t*)(sraw + OFF_VH);
    uint32_t* Vl2 = (uint32_t*)(sraw + OFF_VL);

    const int tid  = threadIdx.x;
    const int w    = tid >> 5;
    const int lane = tid & 31;
    const int g    = lane >> 3;
    const int lr   = lane & 7;

    const size_t base = (size_t)blockIdx.x * (kNQ * kD);
    const float2* Q2 = (const float2*)(gq + base);
    const float2* K2 = (const float2*)(gk + base);
    const float2* V2 = (const float2*)(gv + base);
    float* O = gout + base;

    const int qtb = w * 16;
    const int q0 = qtb + (lane >> 2);
    const int q1 = q0 + 8;
    const bool p0 = q0 < kNQ;
    const bool p1 = q1 < kNQ;
    const int cq = 2 * (lane & 3);

    // ---- Q pipeline: preload kc=0 chunk ----
    float2 qf[2][4];
    {
        const int cb = lane & 3;
        qf[0][0] = p0 ? Q2[q0 * 32 + cb]     : make_float2(0.f, 0.f);
        qf[0][1] = p1 ? Q2[q1 * 32 + cb]     : make_float2(0.f, 0.f);
        qf[0][2] = p0 ? Q2[q0 * 32 + cb + 4] : make_float2(0.f, 0.f);
        qf[0][3] = p1 ? Q2[q1 * 32 + cb + 4] : make_float2(0.f, 0.f);
    }

    // ---- Cooperative K,V load + hi/lo split ----
    for (int idx = tid; idx < (kNK * kD) / 2; idx += 128) {
        const int r = idx >> 5, c2 = idx & 31;
        const float2 k = K2[idx];
        const float2 v = V2[idx];
        const uint32_t kh = packbf2(k.x, k.y);
        const uint32_t vh = packbf2(v.x, v.y);
        const float2 kf = unpackbf2(kh);
        const float2 vf = unpackbf2(vh);
        Kh2[r * 36 + c2] = kh;
        Kl2[r * 36 + c2] = packbf2(k.x - kf.x, k.y - kf.y);
        Vh2[r * 36 + c2] = vh;
        Vl2[r * 36 + c2] = packbf2(v.x - vf.x, v.y - vf.y);
    }
    for (int i = tid; i < 15 * 36; i += 128) {
        const int off = (kNK + i / 36) * 36 + (i % 36);
        Vh2[off] = 0u; Vl2[off] = 0u;
    }
    __syncthreads();   // the ONLY barrier

    // ---- Phase 1: S[16q][64k]; 4-chain MMA scheduling ----
    float acc[8][4];
    #pragma unroll
    for (int i = 0; i < 8; i++)
        #pragma unroll
        for (int j = 0; j < 4; j++) acc[i][j] = 0.0f;
    {
        const uint32_t aKh = cvta_s(sraw + OFF_KH);
        const uint32_t aKl = cvta_s(sraw + OFF_KL);
        #pragma unroll
        for (int kc = 0; kc < 4; kc++) {
            if (kc < 3) {
                const int cb = (kc + 1) * 8 + (lane & 3);
                float2* nb = qf[(kc + 1) & 1];
                nb[0] = p0 ? Q2[q0 * 32 + cb]     : make_float2(0.f, 0.f);
                nb[1] = p1 ? Q2[q1 * 32 + cb]     : make_float2(0.f, 0.f);
                nb[2] = p0 ? Q2[q0 * 32 + cb + 4] : make_float2(0.f, 0.f);
                nb[3] = p1 ? Q2[q1 * 32 + cb + 4] : make_float2(0.f, 0.f);
            }
            uint32_t ah[4], al[4];
            #pragma unroll
            for (int j = 0; j < 4; j++) {
                float2 x = qf[kc & 1][j];
                x.x *= kScale; x.y *= kScale;
                const uint32_t h = packbf2(x.x, x.y);
                const float2 f = unpackbf2(h);
                ah[j] = h;
                al[j] = packbf2(x.x - f.x, x.y - f.y);
            }
            const int d = kc * 16;
            #pragma unroll
            for (int pair = 0; pair < 2; pair++) {
                const int bo0 = ((2 * pair)     * 16 + lr + ((g & 1) << 3)) * kP + d + ((g >> 1) << 3);
                const int bo1 = ((2 * pair + 1) * 16 + lr + ((g & 1) << 3)) * kP + d + ((g >> 1) << 3);
                uint32_t xh0, xh1, xh2, xh3, xl0, xl1, xl2, xl3;   // n-tile pair lo
                uint32_t yh0, yh1, yh2, yh3, yl0, yl1, yl2, yl3;   // n-tile pair hi
                ldsm4(xh0, xh1, xh2, xh3, aKh + bo0 * 2);
                ldsm4(yh0, yh1, yh2, yh3, aKh + bo1 * 2);
                ldsm4(xl0, xl1, xl2, xl3, aKl + bo0 * 2);
                ldsm4(yl0, yl1, yl2, yl3, aKl + bo1 * 2);
                float* c0 = acc[4 * pair];
                float* c1 = acc[4 * pair + 1];
                float* c2 = acc[4 * pair + 2];
                float* c3 = acc[4 * pair + 3];
                const bool full = (pair == 0);   // pair1: c3 = k 56-63, all masked -> skip
                // hh
                mma16816(c0, ah[0], ah[1], ah[2], ah[3], xh0, xh2);
                mma16816(c1, ah[0], ah[1], ah[2], ah[3], xh1, xh3);
                mma16816(c2, ah[0], ah[1], ah[2], ah[3], yh0, yh2);
                if (full) mma16816(c3, ah[0], ah[1], ah[2], ah[3], yh1, yh3);
                // hl
                mma16816(c0, ah[0], ah[1], ah[2], ah[3], xl0, xl2);
                mma16816(c1, ah[0], ah[1], ah[2], ah[3], xl1, xl3);
                mma16816(c2, ah[0], ah[1], ah[2], ah[3], yl0, yl2);
                if (full) mma16816(c3, ah[0], ah[1], ah[2], ah[3], yl1, yl3);
                // lh
                mma16816(c0, al[0], al[1], al[2], al[3], xh0, xh2);
                mma16816(c1, al[0], al[1], al[2], al[3], xh1, xh3);
                mma16816(c2, al[0], al[1], al[2], al[3], yh0, yh2);
                if (full) mma16816(c3, al[0], al[1], al[2], al[3], yh1, yh3);
            }
        }
    }

    // ---- Register softmax (rows q0: acc[..][0,1]; q1: acc[..][2,3]) ----
    float m0 = -CUDART_INF_F, m1 = -CUDART_INF_F;
    #pragma unroll
    for (int nt = 0; nt < 7; nt++) {       // nt=7 fully masked (never computed)
        const int c0 = nt * 8 + cq;
        const bool v0 = (c0 < kNK), v1 = (c0 + 1 < kNK);
        m0 = fmaxf(m0, v0 ? acc[nt][0] : -CUDART_INF_F);
        m0 = fmaxf(m0, v1 ? acc[nt][1] : -CUDART_INF_F);
        m1 = fmaxf(m1, v0 ? acc[nt][2] : -CUDART_INF_F);
        m1 = fmaxf(m1, v1 ? acc[nt][3] : -CUDART_INF_F);
    }
    m0 = fmaxf(m0, __shfl_xor_sync(0xffffffffu, m0, 1));
    m0 = fmaxf(m0, __shfl_xor_sync(0xffffffffu, m0, 2));
    m1 = fmaxf(m1, __shfl_xor_sync(0xffffffffu, m1, 1));
    m1 = fmaxf(m1, __shfl_xor_sync(0xffffffffu, m1, 2));

    float l0 = 0.0f, l1 = 0.0f;
    #pragma unroll
    for (int nt = 0; nt < 7; nt++) {
        const int c0 = nt * 8 + cq;
        const bool v0 = (c0 < kNK), v1 = (c0 + 1 < kNK);
        const float e0 = v0 ? __expf(acc[nt][0] - m0) : 0.0f;
        const float e1 = v1 ? __expf(acc[nt][1] - m0) : 0.0f;
        const float e2 = v0 ? __expf(acc[nt][2] - m1) : 0.0f;
        const float e3 = v1 ? __expf(acc[nt][3] - m1) : 0.0f;
        acc[nt][0] = e0; acc[nt][1] = e1; acc[nt][2] = e2; acc[nt][3] = e3;
        l0 += e0 + e1; l1 += e2 + e3;
    }
    acc[7][0] = acc[7][1] = acc[7][2] = acc[7][3] = 0.0f;
    l0 += __shfl_xor_sync(0xffffffffu, l0, 1);
    l0 += __shfl_xor_sync(0xffffffffu, l0, 2);
    l1 += __shfl_xor_sync(0xffffffffu, l1, 1);
    l1 += __shfl_xor_sync(0xffffffffu, l1, 2);
    const float linv0 = 1.0f / (l0 + kEps);
    const float linv1 = 1.0f / (l1 + kEps);

    // ---- Repack P as A-fragments hi/lo in registers ----
    uint32_t aH[4][4], aL[4][4];
    #pragma unroll
    for (int kc = 0; kc < 4; kc++) {
        #pragma unroll
        for (int t = 0; t < 2; t++) {
            const float e0 = acc[2 * kc + t][0], e1 = acc[2 * kc + t][1];
            const float e2 = acc[2 * kc + t][2], e3 = acc[2 * kc + t][3];
            const uint32_t h01 = packbf2(e0, e1);
            const uint32_t h23 = packbf2(e2, e3);
            const float2 f01 = unpackbf2(h01);
            const float2 f23 = unpackbf2(h23);
            aH[kc][2 * t]     = h01;
            aH[kc][2 * t + 1] = h23;
            aL[kc][2 * t]     = packbf2(e0 - f01.x, e1 - f01.y);
            aL[kc][2 * t + 1] = packbf2(e2 - f23.x, e3 - f23.y);
        }
    }

    // ---- Phase 2: O = P.V; 4-chain scheduling (both n-tiles live) ----
    const uint32_t aVh = cvta_s(sraw + OFF_VH);
    const uint32_t aVl = cvta_s(sraw + OFF_VL);
    #pragma unroll
    for (int half = 0; half < 2; half++) {
        const int db = half * 32;
        float o[4][4];
        #pragma unroll
        for (int i = 0; i < 4; i++)
            #pragma unroll
            for (int j = 0; j < 4; j++) o[i][j] = 0.0f;

        #pragma unroll
        for (int kc = 0; kc < 4; kc++) {
            const int kk = kc * 16;
            const int bo0 = (kk + ((g >> 1) << 3) + lr) * kP + db      + ((g & 1) << 3);
            const int bo1 = (kk + ((g >> 1) << 3) + lr) * kP + db + 16 + ((g & 1) << 3);
            uint32_t xh0, xh1, xh2, xh3, xl0, xl1, xl2, xl3;
            uint32_t yh0, yh1, yh2, yh3, yl0, yl1, yl2, yl3;
            ldsm4t(xh0, xh1, xh2, xh3, aVh + bo0 * 2);
            ldsm4t(yh0, yh1, yh2, yh3, aVh + bo1 * 2);
            ldsm4t(xl0, xl1, xl2, xl3, aVl + bo0 * 2);
            ldsm4t(yl0, yl1, yl2, yl3, aVl + bo1 * 2);
            // hh (4 chains)
            mma16816(o[0], aH[kc][0], aH[kc][1], aH[kc][2], aH[kc][3], xh0, xh2);
            mma16816(o[1], aH[kc][0], aH[kc][1], aH[kc][2], aH[kc][3], xh1, xh3);
            mma16816(o[2], aH[kc][0], aH[kc][1], aH[kc][2], aH[kc][3], yh0, yh2);
            mma16816(o[3], aH[kc][0], aH[kc][1], aH[kc][2], aH[kc][3], yh1, yh3);
            // hl
            mma16816(o[0], aH[kc][0], aH[kc][1], aH[kc][2], aH[kc][3], xl0, xl2);
            mma16816(o[1], aH[kc][0], aH[kc][1], aH[kc][2], aH[kc][3], xl1, xl3);
            mma16816(o[2], aH[kc][0], aH[kc][1], aH[kc][2], aH[kc][3], yl0, yl2);
            mma16816(o[3], aH[kc][0], aH[kc][1], aH[kc][2], aH[kc][3], yl1, yl3);
            // lh
            mma16816(o[0], aL[kc][0], aL[kc][1], aL[kc][2], aL[kc][3], xh0, xh2);
            mma16816(o[1], aL[kc][0], aL[kc][1], aL[kc][2], aL[kc][3], xh1, xh3);
            mma16816(o[2], aL[kc][0], aL[kc][1], aL[kc][2], aL[kc][3], yh0, yh2);
            mma16816(o[3], aL[kc][0], aL[kc][1], aL[kc][2], aL[kc][3], yh1, yh3);
        }

        #pragma unroll
        for (int nt = 0; nt < 4; nt++) {
            const int d = db + nt * 8 + cq;
            if (p0)
                *(float2*)(O + q0 * kD + d) = make_float2(o[nt][0] * linv0, o[nt][1] * linv0);
            if (p1)
                *(float2*)(O + q1 * kD + d) = make_float2(o[nt][2] * linv1, o[nt][3] * linv1);
        }
    }
}

extern "C" void kernel_launch(void* const* d_in, const int* in_sizes, int n_in,
                              void* d_out, int out_size)
{
    const float* q = (const float*)d_in[0];
    const float* k = (const float*)d_in[1];
    const float* v = (const float*)d_in[2];
    float* out = (float*)d_out;

    const int bh = in_sizes[0] / (kNQ * kD);   // 4096
    attn49_v9<<<bh, 128>>>(q, k, v, out);
}

// round 11
// speedup vs baseline: 1.1891x; 1.0287x over previous
#include <cuda_runtime.h>
#include <cuda_bf16.h>
#include <math_constants.h>
#include <cstdint>

// Attention B=256,H=16,Nq=Nk=49,D=64 fp32. One CTA (128 thr, 4 warps) per (b,h).
// bf16 hi/lo 3-term tensor-core GEMMs; warp w owns q rows [16w,16w+16).
// R11: shared-guard smem layout [Kh][Kl][Vh][Vl][zero guard] (49-row arrays,
// LDSM row-overflow spills into the next array; all overflow positions hit
// masked/zero coefficients) -> 30.4KB, launch_bounds(128,7) -> 7 CTAs/SM.
// log2e folded into Q scale -> exp2f softmax. 4-chain MMA scheduling (R9).

namespace {
constexpr int kNQ = 49, kNK = 49, kD = 64;
constexpr int kP  = 72;                  // bf16 pitch (144B = 9*16)
constexpr float kQscale = 0.125f * 1.4426950408889634f;  // scale * log2(e)
constexpr float kEps    = 1e-9f;
constexpr int kROWB = kP * 2;            // 144 bytes per row
constexpr int kARR  = 49 * kROWB;        // 7056 per operand array
constexpr int OFF_KH = 0;
constexpr int OFF_KL = OFF_KH + kARR;    // 7056
constexpr int OFF_VH = OFF_KL + kARR;    // 14112
constexpr int OFF_VL = OFF_VH + kARR;    // 21168
constexpr int OFF_GD = OFF_VL + kARR;    // 28224 (15-row zero guard)
constexpr int SMEM_BYTES = OFF_GD + 15 * kROWB;   // 30384
}

__device__ __forceinline__ uint32_t cvta_s(const void* p) {
    return (uint32_t)__cvta_generic_to_shared(p);
}
__device__ __forceinline__ void ldsm4(uint32_t& r0, uint32_t& r1, uint32_t& r2, uint32_t& r3, uint32_t a) {
    asm volatile("ldmatrix.sync.aligned.m8n8.x4.shared.b16 {%0,%1,%2,%3}, [%4];\n"
                 : "=r"(r0), "=r"(r1), "=r"(r2), "=r"(r3) : "r"(a));
}
__device__ __forceinline__ void ldsm4t(uint32_t& r0, uint32_t& r1, uint32_t& r2, uint32_t& r3, uint32_t a) {
    asm volatile("ldmatrix.sync.aligned.m8n8.x4.trans.shared.b16 {%0,%1,%2,%3}, [%4];\n"
                 : "=r"(r0), "=r"(r1), "=r"(r2), "=r"(r3) : "r"(a));
}
__device__ __forceinline__ void mma16816(float* c,
                                         uint32_t a0, uint32_t a1, uint32_t a2, uint32_t a3,
                                         uint32_t b0, uint32_t b1) {
    asm volatile("mma.sync.aligned.m16n8k16.row.col.f32.bf16.bf16.f32 "
                 "{%0,%1,%2,%3}, {%4,%5,%6,%7}, {%8,%9}, {%0,%1,%2,%3};\n"
                 : "+f"(c[0]), "+f"(c[1]), "+f"(c[2]), "+f"(c[3])
                 : "r"(a0), "r"(a1), "r"(a2), "r"(a3), "r"(b0), "r"(b1));
}
__device__ __forceinline__ uint32_t packbf2(float lo, float hi) {
    uint32_t r;
    asm("cvt.rn.bf16x2.f32 %0, %1, %2;" : "=r"(r) : "f"(hi), "f"(lo));
    return r;
}
__device__ __forceinline__ float2 unpackbf2(uint32_t h) {
    return make_float2(__uint_as_float(h << 16), __uint_as_float(h & 0xffff0000u));
}

__global__ __launch_bounds__(128, 7)
void attn49_v11(const float* __restrict__ gq,
                const float* __restrict__ gk,
                const float* __restrict__ gv,
                float* __restrict__ gout)
{
    __shared__ __align__(16) char sraw[SMEM_BYTES];
    uint32_t* Kh2 = (uint32_t*)(sraw + OFF_KH);
    uint32_t* Kl2 = (uint32_t*)(sraw + OFF_KL);
    uint32_t* Vh2 = (uint32_t*)(sraw + OFF_VH);
    uint32_t* Vl2 = (uint32_t*)(sraw + OFF_VL);

    const int tid  = threadIdx.x;
    const int w    = tid >> 5;
    const int lane = tid & 31;
    const int g    = lane >> 3;
    const int lr   = lane & 7;

    const size_t base = (size_t)blockIdx.x * (kNQ * kD);
    const float2* Q2 = (const float2*)(gq + base);
    const float2* K2 = (const float2*)(gk + base);
    const float2* V2 = (const float2*)(gv + base);
    float* O = gout + base;

    const int qtb = w * 16;
    const int q0 = qtb + (lane >> 2);
    const int q1 = q0 + 8;
    const bool p0 = q0 < kNQ;
    const bool p1 = q1 < kNQ;
    const int cq = 2 * (lane & 3);

    // ---- Cooperative K,V load + hi/lo split (49-row arrays) ----
    for (int idx = tid; idx < (kNK * kD) / 2; idx += 128) {
        const int r = idx >> 5, c2 = idx & 31;
        const float2 k = K2[idx];
        const float2 v = V2[idx];
        const uint32_t kh = packbf2(k.x, k.y);
        const uint32_t vh = packbf2(v.x, v.y);
        const float2 kf = unpackbf2(kh);
        const float2 vf = unpackbf2(vh);
        Kh2[r * 36 + c2] = kh;
        Kl2[r * 36 + c2] = packbf2(k.x - kf.x, k.y - kf.y);
        Vh2[r * 36 + c2] = vh;
        Vl2[r * 36 + c2] = packbf2(v.x - vf.x, v.y - vf.y);
    }
    // zero the single shared guard (Vl overflow target)
    for (int i = tid; i < 15 * 36; i += 128)
        ((uint32_t*)(sraw + OFF_GD))[i] = 0u;
    __syncthreads();   // the ONLY barrier

    // ---- Phase 1: S[16q][64k]; 4-chain MMA scheduling; Q streamed per kc ----
    float acc[8][4];
    #pragma unroll
    for (int i = 0; i < 8; i++)
        #pragma unroll
        for (int j = 0; j < 4; j++) acc[i][j] = 0.0f;
    {
        const uint32_t aKh = cvta_s(sraw + OFF_KH);
        const uint32_t aKl = cvta_s(sraw + OFF_KL);
        #pragma unroll
        for (int kc = 0; kc < 4; kc++) {
            // load this kc's Q chunk (scaled by 1/8 * log2e), split hi/lo
            uint32_t ah[4], al[4];
            {
                const int cb = kc * 8 + (lane & 3);
                float2 x0 = p0 ? Q2[q0 * 32 + cb]     : make_float2(0.f, 0.f);
                float2 x1 = p1 ? Q2[q1 * 32 + cb]     : make_float2(0.f, 0.f);
                float2 x2 = p0 ? Q2[q0 * 32 + cb + 4] : make_float2(0.f, 0.f);
                float2 x3 = p1 ? Q2[q1 * 32 + cb + 4] : make_float2(0.f, 0.f);
                x0.x *= kQscale; x0.y *= kQscale; x1.x *= kQscale; x1.y *= kQscale;
                x2.x *= kQscale; x2.y *= kQscale; x3.x *= kQscale; x3.y *= kQscale;
                const uint32_t h0 = packbf2(x0.x, x0.y);
                const uint32_t h1 = packbf2(x1.x, x1.y);
                const uint32_t h2 = packbf2(x2.x, x2.y);
                const uint32_t h3 = packbf2(x3.x, x3.y);
                const float2 f0 = unpackbf2(h0), f1 = unpackbf2(h1);
                const float2 f2 = unpackbf2(h2), f3 = unpackbf2(h3);
                ah[0] = h0; ah[1] = h1; ah[2] = h2; ah[3] = h3;
                al[0] = packbf2(x0.x - f0.x, x0.y - f0.y);
                al[1] = packbf2(x1.x - f1.x, x1.y - f1.y);
                al[2] = packbf2(x2.x - f2.x, x2.y - f2.y);
                al[3] = packbf2(x3.x - f3.x, x3.y - f3.y);
            }
            const int d = kc * 16;
            #pragma unroll
            for (int pair = 0; pair < 2; pair++) {
                const int bo0 = ((2 * pair)     * 16 + lr + ((g & 1) << 3)) * kP + d + ((g >> 1) << 3);
                const int bo1 = ((2 * pair + 1) * 16 + lr + ((g & 1) << 3)) * kP + d + ((g >> 1) << 3);
                uint32_t xh0, xh1, xh2, xh3, xl0, xl1, xl2, xl3;
                uint32_t yh0, yh1, yh2, yh3, yl0, yl1, yl2, yl3;
                ldsm4(xh0, xh1, xh2, xh3, aKh + bo0 * 2);   // row>48 spills into Kl: finite, masked
                ldsm4(yh0, yh1, yh2, yh3, aKh + bo1 * 2);
                ldsm4(xl0, xl1, xl2, xl3, aKl + bo0 * 2);   // spills into Vh: finite, masked
                ldsm4(yl0, yl1, yl2, yl3, aKl + bo1 * 2);
                float* c0 = acc[4 * pair];
                float* c1 = acc[4 * pair + 1];
                float* c2 = acc[4 * pair + 2];
                float* c3 = acc[4 * pair + 3];
                const bool full = (pair == 0);   // pair1 c3 = k 56-63, all masked -> skip
                mma16816(c0, ah[0], ah[1], ah[2], ah[3], xh0, xh2);
                mma16816(c1, ah[0], ah[1], ah[2], ah[3], xh1, xh3);
                mma16816(c2, ah[0], ah[1], ah[2], ah[3], yh0, yh2);
                if (full) mma16816(c3, ah[0], ah[1], ah[2], ah[3], yh1, yh3);
                mma16816(c0, ah[0], ah[1], ah[2], ah[3], xl0, xl2);
                mma16816(c1, ah[0], ah[1], ah[2], ah[3], xl1, xl3);
                mma16816(c2, ah[0], ah[1], ah[2], ah[3], yl0, yl2);
                if (full) mma16816(c3, ah[0], ah[1], ah[2], ah[3], yl1, yl3);
                mma16816(c0, al[0], al[1], al[2], al[3], xh0, xh2);
                mma16816(c1, al[0], al[1], al[2], al[3], xh1, xh3);
                mma16816(c2, al[0], al[1], al[2], al[3], yh0, yh2);
                if (full) mma16816(c3, al[0], al[1], al[2], al[3], yh1, yh3);
            }
        }
    }

    // ---- Register softmax in log2 domain (rows q0: acc[..][0,1]; q1: [2,3]) ----
    float m0 = -CUDART_INF_F, m1 = -CUDART_INF_F;
    #pragma unroll
    for (int nt = 0; nt < 7; nt++) {
        const int c0 = nt * 8 + cq;
        const bool v0 = (c0 < kNK), v1 = (c0 + 1 < kNK);
        m0 = fmaxf(m0, v0 ? acc[nt][0] : -CUDART_INF_F);
        m0 = fmaxf(m0, v1 ? acc[nt][1] : -CUDART_INF_F);
        m1 = fmaxf(m1, v0 ? acc[nt][2] : -CUDART_INF_F);
        m1 = fmaxf(m1, v1 ? acc[nt][3] : -CUDART_INF_F);
    }
    m0 = fmaxf(m0, __shfl_xor_sync(0xffffffffu, m0, 1));
    m0 = fmaxf(m0, __shfl_xor_sync(0xffffffffu, m0, 2));
    m1 = fmaxf(m1, __shfl_xor_sync(0xffffffffu, m1, 1));
    m1 = fmaxf(m1, __shfl_xor_sync(0xffffffffu, m1, 2));

    float l0 = 0.0f, l1 = 0.0f;
    #pragma unroll
    for (int nt = 0; nt < 7; nt++) {
        const int c0 = nt * 8 + cq;
        const bool v0 = (c0 < kNK), v1 = (c0 + 1 < kNK);
        const float e0 = v0 ? exp2f(acc[nt][0] - m0) : 0.0f;
        const float e1 = v1 ? exp2f(acc[nt][1] - m0) : 0.0f;
        const float e2 = v0 ? exp2f(acc[nt][2] - m1) : 0.0f;
        const float e3 = v1 ? exp2f(acc[nt][3] - m1) : 0.0f;
        acc[nt][0] = e0; acc[nt][1] = e1; acc[nt][2] = e2; acc[nt][3] = e3;
        l0 += e0 + e1; l1 += e2 + e3;
    }
    acc[7][0] = acc[7][1] = acc[7][2] = acc[7][3] = 0.0f;
    l0 += __shfl_xor_sync(0xffffffffu, l0, 1);
    l0 += __shfl_xor_sync(0xffffffffu, l0, 2);
    l1 += __shfl_xor_sync(0xffffffffu, l1, 1);
    l1 += __shfl_xor_sync(0xffffffffu, l1, 2);
    const float linv0 = 1.0f / (l0 + kEps);
    const float linv1 = 1.0f / (l1 + kEps);

    // ---- Repack P as A-fragments hi/lo in registers ----
    uint32_t aH[4][4], aL[4][4];
    #pragma unroll
    for (int kc = 0; kc < 4; kc++) {
        #pragma unroll
        for (int t = 0; t < 2; t++) {
            const float e0 = acc[2 * kc + t][0], e1 = acc[2 * kc + t][1];
            const float e2 = acc[2 * kc + t][2], e3 = acc[2 * kc + t][3];
            const uint32_t h01 = packbf2(e0, e1);
            const uint32_t h23 = packbf2(e2, e3);
            const float2 f01 = unpackbf2(h01);
            const float2 f23 = unpackbf2(h23);
            aH[kc][2 * t]     = h01;
            aH[kc][2 * t + 1] = h23;
            aL[kc][2 * t]     = packbf2(e0 - f01.x, e1 - f01.y);
            aL[kc][2 * t + 1] = packbf2(e2 - f23.x, e3 - f23.y);
        }
    }

    // ---- Phase 2: O = P.V; 4-chain scheduling ----
    const uint32_t aVh = cvta_s(sraw + OFF_VH);
    const uint32_t aVl = cvta_s(sraw + OFF_VL);
    #pragma unroll
    for (int half = 0; half < 2; half++) {
        const int db = half * 32;
        float o[4][4];
        #pragma unroll
        for (int i = 0; i < 4; i++)
            #pragma unroll
            for (int j = 0; j < 4; j++) o[i][j] = 0.0f;

        #pragma unroll
        for (int kc = 0; kc < 4; kc++) {
            const int kk = kc * 16;
            const int bo0 = (kk + ((g >> 1) << 3) + lr) * kP + db      + ((g & 1) << 3);
            const int bo1 = (kk + ((g >> 1) << 3) + lr) * kP + db + 16 + ((g & 1) << 3);
            uint32_t xh0, xh1, xh2, xh3, xl0, xl1, xl2, xl3;
            uint32_t yh0, yh1, yh2, yh3, yl0, yl1, yl2, yl3;
            ldsm4t(xh0, xh1, xh2, xh3, aVh + bo0 * 2);   // row>48 spills into Vl: finite, P=0
            ldsm4t(yh0, yh1, yh2, yh3, aVh + bo1 * 2);
            ldsm4t(xl0, xl1, xl2, xl3, aVl + bo0 * 2);   // spills into zero guard
            ldsm4t(yl0, yl1, yl2, yl3, aVl + bo1 * 2);
            mma16816(o[0], aH[kc][0], aH[kc][1], aH[kc][2], aH[kc][3], xh0, xh2);
            mma16816(o[1], aH[kc][0], aH[kc][1], aH[kc][2], aH[kc][3], xh1, xh3);
            mma16816(o[2], aH[kc][0], aH[kc][1], aH[kc][2], aH[kc][3], yh0, yh2);
            mma16816(o[3], aH[kc][0], aH[kc][1], aH[kc][2], aH[kc][3], yh1, yh3);
            mma16816(o[0], aH[kc][0], aH[kc][1], aH[kc][2], aH[kc][3], xl0, xl2);
            mma16816(o[1], aH[kc][0], aH[kc][1], aH[kc][2], aH[kc][3], xl1, xl3);
            mma16816(o[2], aH[kc][0], aH[kc][1], aH[kc][2], aH[kc][3], yl0, yl2);
            mma16816(o[3], aH[kc][0], aH[kc][1], aH[kc][2], aH[kc][3], yl1, yl3);
            mma16816(o[0], aL[kc][0], aL[kc][1], aL[kc][2], aL[kc][3], xh0, xh2);
            mma16816(o[1], aL[kc][0], aL[kc][1], aL[kc][2], aL[kc][3], xh1, xh3);
            mma16816(o[2], aL[kc][0], aL[kc][1], aL[kc][2], aL[kc][3], yh0, yh2);
            mma16816(o[3], aL[kc][0], aL[kc][1], aL[kc][2], aL[kc][3], yh1, yh3);
        }

        #pragma unroll
        for (int nt = 0; nt < 4; nt++) {
            const int d = db + nt * 8 + cq;
            if (p0)
                *(float2*)(O + q0 * kD + d) = make_float2(o[nt][0] * linv0, o[nt][1] * linv0);
            if (p1)
                *(float2*)(O + q1 * kD + d) = make_float2(o[nt][2] * linv1, o[nt][3] * linv1);
        }
    }
}

extern "C" void kernel_launch(void* const* d_in, const int* in_sizes, int n_in,
                              void* d_out, int out_size)
{
    const float* q = (const float*)d_in[0];
    const float* k = (const float*)d_in[1];
    const float* v = (const float*)d_in[2];
    float* out = (float*)d_out;

    const int bh = in_sizes[0] / (kNQ * kD);   // 4096
    attn49_v11<<<bh, 128>>>(q, k, v, out);
}

// round 12
// speedup vs baseline: 1.4375x; 1.2089x over previous
#include <cuda_runtime.h>
#include <cuda_bf16.h>
#include <math_constants.h>
#include <cstdint>

// Attention B=256,H=16,Nq=Nk=49,D=64 fp32. One CTA (128 thr, 4 warps) per (b,h).
// bf16 hi/lo 3-term tensor-core GEMMs; warp w owns q rows [16w,16w+16).
// R12: key 48 folded out of phase-2 MMA as scalar fp32 rank-1 update
// (p48 via quad shuffle, V[48] re-read from gmem -> L1 hit). Phase2 kc 0-2
// only (72 MMAs). Phase1 48-55 key tile via ldsm.x2. Smem 27.9KB, no guard,
// launch_bounds(128,8) -> target 8 CTAs/SM. float4 loads + STS.64.

namespace {
constexpr int kNQ = 49, kNK = 49, kD = 64;
constexpr int kP  = 72;                     // bf16 pitch (144B = 9*16)
constexpr float kQscale = 0.125f * 1.4426950408889634f;  // scale * log2(e)
constexpr float kEps    = 1e-9f;
constexpr int kROWB = 144;
constexpr int OFF_KH = 0;
constexpr int OFF_KL = 49 * kROWB;              // 7056
constexpr int OFF_VH = 2 * 49 * kROWB;          // 14112
constexpr int OFF_VL = OFF_VH + 48 * kROWB;     // 21024
constexpr int SMEM_BYTES = OFF_VL + 48 * kROWB; // 27936
}

__device__ __forceinline__ uint32_t cvta_s(const void* p) {
    return (uint32_t)__cvta_generic_to_shared(p);
}
__device__ __forceinline__ void ldsm4(uint32_t& r0, uint32_t& r1, uint32_t& r2, uint32_t& r3, uint32_t a) {
    asm volatile("ldmatrix.sync.aligned.m8n8.x4.shared.b16 {%0,%1,%2,%3}, [%4];\n"
                 : "=r"(r0), "=r"(r1), "=r"(r2), "=r"(r3) : "r"(a));
}
__device__ __forceinline__ void ldsm2(uint32_t& r0, uint32_t& r1, uint32_t a) {
    asm volatile("ldmatrix.sync.aligned.m8n8.x2.shared.b16 {%0,%1}, [%2];\n"
                 : "=r"(r0), "=r"(r1) : "r"(a));
}
__device__ __forceinline__ void ldsm4t(uint32_t& r0, uint32_t& r1, uint32_t& r2, uint32_t& r3, uint32_t a) {
    asm volatile("ldmatrix.sync.aligned.m8n8.x4.trans.shared.b16 {%0,%1,%2,%3}, [%4];\n"
                 : "=r"(r0), "=r"(r1), "=r"(r2), "=r"(r3) : "r"(a));
}
__device__ __forceinline__ void mma16816(float* c,
                                         uint32_t a0, uint32_t a1, uint32_t a2, uint32_t a3,
                                         uint32_t b0, uint32_t b1) {
    asm volatile("mma.sync.aligned.m16n8k16.row.col.f32.bf16.bf16.f32 "
                 "{%0,%1,%2,%3}, {%4,%5,%6,%7}, {%8,%9}, {%0,%1,%2,%3};\n"
                 : "+f"(c[0]), "+f"(c[1]), "+f"(c[2]), "+f"(c[3])
                 : "r"(a0), "r"(a1), "r"(a2), "r"(a3), "r"(b0), "r"(b1));
}
__device__ __forceinline__ uint32_t packbf2(float lo, float hi) {
    uint32_t r;
    asm("cvt.rn.bf16x2.f32 %0, %1, %2;" : "=r"(r) : "f"(hi), "f"(lo));
    return r;
}
__device__ __forceinline__ float2 unpackbf2(uint32_t h) {
    return make_float2(__uint_as_float(h << 16), __uint_as_float(h & 0xffff0000u));
}

__global__ __launch_bounds__(128, 8)
void attn49_v12(const float* __restrict__ gq,
                const float* __restrict__ gk,
                const float* __restrict__ gv,
                float* __restrict__ gout)
{
    __shared__ __align__(16) char sraw[SMEM_BYTES];

    const int tid  = threadIdx.x;
    const int w    = tid >> 5;
    const int lane = tid & 31;
    const int g    = lane >> 3;
    const int lr   = lane & 7;

    const size_t base = (size_t)blockIdx.x * (kNQ * kD);
    const float2* Q2 = (const float2*)(gq + base);
    const float4* K4 = (const float4*)(gk + base);
    const float4* V4 = (const float4*)(gv + base);
    float* O = gout + base;

    const int qtb = w * 16;
    const int q0 = qtb + (lane >> 2);
    const int q1 = q0 + 8;
    const bool p0 = q0 < kNQ;
    const bool p1 = q1 < kNQ;
    const int cq = 2 * (lane & 3);

    // ---- K (rows 0-48) and V (rows 0-47) load + hi/lo split, float4/STS.64 ----
    for (int idx = tid; idx < 49 * 16; idx += 128) {
        const int r = idx >> 4, c4 = idx & 15;
        const float4 k = K4[idx];
        {
            const uint32_t h01 = packbf2(k.x, k.y);
            const uint32_t h23 = packbf2(k.z, k.w);
            const float2 f01 = unpackbf2(h01), f23 = unpackbf2(h23);
            *(uint2*)(sraw + OFF_KH + r * kROWB + c4 * 8) = make_uint2(h01, h23);
            *(uint2*)(sraw + OFF_KL + r * kROWB + c4 * 8) =
                make_uint2(packbf2(k.x - f01.x, k.y - f01.y),
                           packbf2(k.z - f23.x, k.w - f23.y));
        }
        if (r < 48) {
            const float4 v = V4[idx];
            const uint32_t h01 = packbf2(v.x, v.y);
            const uint32_t h23 = packbf2(v.z, v.w);
            const float2 f01 = unpackbf2(h01), f23 = unpackbf2(h23);
            *(uint2*)(sraw + OFF_VH + r * kROWB + c4 * 8) = make_uint2(h01, h23);
            *(uint2*)(sraw + OFF_VL + r * kROWB + c4 * 8) =
                make_uint2(packbf2(v.x - f01.x, v.y - f01.y),
                           packbf2(v.z - f23.x, v.w - f23.y));
        }
    }
    __syncthreads();   // the ONLY barrier

    // ---- Phase 1: S[16q][56k] (acc[0..6]); tile 48-55 via ldsm.x2 ----
    float acc[7][4];
    #pragma unroll
    for (int i = 0; i < 7; i++)
        #pragma unroll
        for (int j = 0; j < 4; j++) acc[i][j] = 0.0f;
    {
        const uint32_t aKh = cvta_s(sraw + OFF_KH);
        const uint32_t aKl = cvta_s(sraw + OFF_KL);
        const int ro = lr + ((g & 1) << 3);
        const int co = (g >> 1) << 3;
        #pragma unroll
        for (int kc = 0; kc < 4; kc++) {
            // Q chunk (scaled by 1/8*log2e), hi/lo split in regs
            uint32_t ah[4], al[4];
            {
                const int cb = kc * 8 + (lane & 3);
                float2 x0 = p0 ? Q2[q0 * 32 + cb]     : make_float2(0.f, 0.f);
                float2 x1 = p1 ? Q2[q1 * 32 + cb]     : make_float2(0.f, 0.f);
                float2 x2 = p0 ? Q2[q0 * 32 + cb + 4] : make_float2(0.f, 0.f);
                float2 x3 = p1 ? Q2[q1 * 32 + cb + 4] : make_float2(0.f, 0.f);
                x0.x *= kQscale; x0.y *= kQscale; x1.x *= kQscale; x1.y *= kQscale;
                x2.x *= kQscale; x2.y *= kQscale; x3.x *= kQscale; x3.y *= kQscale;
                ah[0] = packbf2(x0.x, x0.y); ah[1] = packbf2(x1.x, x1.y);
                ah[2] = packbf2(x2.x, x2.y); ah[3] = packbf2(x3.x, x3.y);
                const float2 f0 = unpackbf2(ah[0]), f1 = unpackbf2(ah[1]);
                const float2 f2 = unpackbf2(ah[2]), f3 = unpackbf2(ah[3]);
                al[0] = packbf2(x0.x - f0.x, x0.y - f0.y);
                al[1] = packbf2(x1.x - f1.x, x1.y - f1.y);
                al[2] = packbf2(x2.x - f2.x, x2.y - f2.y);
                al[3] = packbf2(x3.x - f3.x, x3.y - f3.y);
            }
            const int d = kc * 16;
            // pair 0: key rows 0-31 (acc0..3), 4 chains
            {
                const int b0 = ro * kP + d + co;
                const int b1 = (16 + ro) * kP + d + co;
                uint32_t xh0, xh1, xh2, xh3, xl0, xl1, xl2, xl3;
                uint32_t yh0, yh1, yh2, yh3, yl0, yl1, yl2, yl3;
                ldsm4(xh0, xh1, xh2, xh3, aKh + b0 * 2);
                ldsm4(yh0, yh1, yh2, yh3, aKh + b1 * 2);
                ldsm4(xl0, xl1, xl2, xl3, aKl + b0 * 2);
                ldsm4(yl0, yl1, yl2, yl3, aKl + b1 * 2);
                mma16816(acc[0], ah[0], ah[1], ah[2], ah[3], xh0, xh2);
                mma16816(acc[1], ah[0], ah[1], ah[2], ah[3], xh1, xh3);
                mma16816(acc[2], ah[0], ah[1], ah[2], ah[3], yh0, yh2);
                mma16816(acc[3], ah[0], ah[1], ah[2], ah[3], yh1, yh3);
                mma16816(acc[0], ah[0], ah[1], ah[2], ah[3], xl0, xl2);
                mma16816(acc[1], ah[0], ah[1], ah[2], ah[3], xl1, xl3);
                mma16816(acc[2], ah[0], ah[1], ah[2], ah[3], yl0, yl2);
                mma16816(acc[3], ah[0], ah[1], ah[2], ah[3], yl1, yl3);
                mma16816(acc[0], al[0], al[1], al[2], al[3], xh0, xh2);
                mma16816(acc[1], al[0], al[1], al[2], al[3], xh1, xh3);
                mma16816(acc[2], al[0], al[1], al[2], al[3], yh0, yh2);
                mma16816(acc[3], al[0], al[1], al[2], al[3], yh1, yh3);
            }
            // pair 1: key rows 32-47 (acc4,5) x4 + rows 48-55 (acc6) x2
            {
                const int b2 = (32 + ro) * kP + d + co;
                const int b3 = (48 + lr) * kP + d + ((g & 1) << 3);   // x2: 7-row spill, masked
                uint32_t zh0, zh1, zh2, zh3, zl0, zl1, zl2, zl3;
                uint32_t wh0, wh1, wl0, wl1;
                ldsm4(zh0, zh1, zh2, zh3, aKh + b2 * 2);
                ldsm2(wh0, wh1, aKh + b3 * 2);
                ldsm4(zl0, zl1, zl2, zl3, aKl + b2 * 2);
                ldsm2(wl0, wl1, aKl + b3 * 2);
                mma16816(acc[4], ah[0], ah[1], ah[2], ah[3], zh0, zh2);
                mma16816(acc[5], ah[0], ah[1], ah[2], ah[3], zh1, zh3);
                mma16816(acc[6], ah[0], ah[1], ah[2], ah[3], wh0, wh1);
                mma16816(acc[4], ah[0], ah[1], ah[2], ah[3], zl0, zl2);
                mma16816(acc[5], ah[0], ah[1], ah[2], ah[3], zl1, zl3);
                mma16816(acc[6], ah[0], ah[1], ah[2], ah[3], wl0, wl1);
                mma16816(acc[4], al[0], al[1], al[2], al[3], zh0, zh2);
                mma16816(acc[5], al[0], al[1], al[2], al[3], zh1, zh3);
                mma16816(acc[6], al[0], al[1], al[2], al[3], wh0, wh1);
            }
        }
    }

    // ---- Register softmax, log2 domain ----
    float m0 = -CUDART_INF_F, m1 = -CUDART_INF_F;
    #pragma unroll
    for (int nt = 0; nt < 7; nt++) {
        const int c0 = nt * 8 + cq;
        const bool v0 = (c0 < kNK), v1 = (c0 + 1 < kNK);
        m0 = fmaxf(m0, v0 ? acc[nt][0] : -CUDART_INF_F);
        m0 = fmaxf(m0, v1 ? acc[nt][1] : -CUDART_INF_F);
        m1 = fmaxf(m1, v0 ? acc[nt][2] : -CUDART_INF_F);
        m1 = fmaxf(m1, v1 ? acc[nt][3] : -CUDART_INF_F);
    }
    m0 = fmaxf(m0, __shfl_xor_sync(0xffffffffu, m0, 1));
    m0 = fmaxf(m0, __shfl_xor_sync(0xffffffffu, m0, 2));
    m1 = fmaxf(m1, __shfl_xor_sync(0xffffffffu, m1, 1));
    m1 = fmaxf(m1, __shfl_xor_sync(0xffffffffu, m1, 2));

    float l0 = 0.0f, l1 = 0.0f;
    #pragma unroll
    for (int nt = 0; nt < 7; nt++) {
        const int c0 = nt * 8 + cq;
        const bool v0 = (c0 < kNK), v1 = (c0 + 1 < kNK);
        const float e0 = v0 ? exp2f(acc[nt][0] - m0) : 0.0f;
        const float e1 = v1 ? exp2f(acc[nt][1] - m0) : 0.0f;
        const float e2 = v0 ? exp2f(acc[nt][2] - m1) : 0.0f;
        const float e3 = v1 ? exp2f(acc[nt][3] - m1) : 0.0f;
        acc[nt][0] = e0; acc[nt][1] = e1; acc[nt][2] = e2; acc[nt][3] = e3;
        l0 += e0 + e1; l1 += e2 + e3;
    }
    l0 += __shfl_xor_sync(0xffffffffu, l0, 1);
    l0 += __shfl_xor_sync(0xffffffffu, l0, 2);
    l1 += __shfl_xor_sync(0xffffffffu, l1, 1);
    l1 += __shfl_xor_sync(0xffffffffu, l1, 2);
    const float linv0 = 1.0f / (l0 + kEps);
    const float linv1 = 1.0f / (l1 + kEps);

    // p48 = exp value for key 48 (held by quad leader, col 48 = nt6,cq0)
    const float p48_0 = __shfl_sync(0xffffffffu, acc[6][0], lane & ~3);
    const float p48_1 = __shfl_sync(0xffffffffu, acc[6][2], lane & ~3);

    // ---- Repack P (cols 0-47) as A-fragments hi/lo in registers ----
    uint32_t aH[3][4], aL[3][4];
    #pragma unroll
    for (int kc = 0; kc < 3; kc++) {
        #pragma unroll
        for (int t = 0; t < 2; t++) {
            const float e0 = acc[2 * kc + t][0], e1 = acc[2 * kc + t][1];
            const float e2 = acc[2 * kc + t][2], e3 = acc[2 * kc + t][3];
            const uint32_t h01 = packbf2(e0, e1);
            const uint32_t h23 = packbf2(e2, e3);
            const float2 f01 = unpackbf2(h01);
            const float2 f23 = unpackbf2(h23);
            aH[kc][2 * t]     = h01;
            aH[kc][2 * t + 1] = h23;
            aL[kc][2 * t]     = packbf2(e0 - f01.x, e1 - f01.y);
            aL[kc][2 * t + 1] = packbf2(e2 - f23.x, e3 - f23.y);
        }
    }

    // ---- Phase 2: O = P.V over k 0-47 (MMA) + p48*V[48] (scalar fp32) ----
    const uint32_t aVh = cvta_s(sraw + OFF_VH);
    const uint32_t aVl = cvta_s(sraw + OFF_VL);
    const float2* V48 = (const float2*)(gv + base + 48 * kD);
    #pragma unroll
    for (int half = 0; half < 2; half++) {
        const int db = half * 32;
        // prefetch V row 48 (gmem, L1-hit) for this half's columns
        float2 vv[4];
        #pragma unroll
        for (int nt = 0; nt < 4; nt++)
            vv[nt] = V48[(db >> 1) + nt * 4 + (cq >> 1)];

        float o[4][4];
        #pragma unroll
        for (int i = 0; i < 4; i++)
            #pragma unroll
            for (int j = 0; j < 4; j++) o[i][j] = 0.0f;

        #pragma unroll
        for (int kc = 0; kc < 3; kc++) {
            const int kk = kc * 16;
            const int bo0 = (kk + ((g >> 1) << 3) + lr) * kP + db      + ((g & 1) << 3);
            const int bo1 = (kk + ((g >> 1) << 3) + lr) * kP + db + 16 + ((g & 1) << 3);
            uint32_t xh0, xh1, xh2, xh3, xl0, xl1, xl2, xl3;
            uint32_t yh0, yh1, yh2, yh3, yl0, yl1, yl2, yl3;
            ldsm4t(xh0, xh1, xh2, xh3, aVh + bo0 * 2);
            ldsm4t(yh0, yh1, yh2, yh3, aVh + bo1 * 2);
            ldsm4t(xl0, xl1, xl2, xl3, aVl + bo0 * 2);
            ldsm4t(yl0, yl1, yl2, yl3, aVl + bo1 * 2);
            mma16816(o[0], aH[kc][0], aH[kc][1], aH[kc][2], aH[kc][3], xh0, xh2);
            mma16816(o[1], aH[kc][0], aH[kc][1], aH[kc][2], aH[kc][3], xh1, xh3);
            mma16816(o[2], aH[kc][0], aH[kc][1], aH[kc][2], aH[kc][3], yh0, yh2);
            mma16816(o[3], aH[kc][0], aH[kc][1], aH[kc][2], aH[kc][3], yh1, yh3);
            mma16816(o[0], aH[kc][0], aH[kc][1], aH[kc][2], aH[kc][3], xl0, xl2);
            mma16816(o[1], aH[kc][0], aH[kc][1], aH[kc][2], aH[kc][3], xl1, xl3);
            mma16816(o[2], aH[kc][0], aH[kc][1], aH[kc][2], aH[kc][3], yl0, yl2);
            mma16816(o[3], aH[kc][0], aH[kc][1], aH[kc][2], aH[kc][3], yl1, yl3);
            mma16816(o[0], aL[kc][0], aL[kc][1], aL[kc][2], aL[kc][3], xh0, xh2);
            mma16816(o[1], aL[kc][0], aL[kc][1], aL[kc][2], aL[kc][3], xh1, xh3);
            mma16816(o[2], aL[kc][0], aL[kc][1], aL[kc][2], aL[kc][3], yh0, yh2);
            mma16816(o[3], aL[kc][0], aL[kc][1], aL[kc][2], aL[kc][3], yh1, yh3);
        }

        #pragma unroll
        for (int nt = 0; nt < 4; nt++) {
            const int d = db + nt * 8 + cq;
            if (p0)
                *(float2*)(O + q0 * kD + d) =
                    make_float2((o[nt][0] + p48_0 * vv[nt].x) * linv0,
                                (o[nt][1] + p48_0 * vv[nt].y) * linv0);
            if (p1)
                *(float2*)(O + q1 * kD + d) =
                    make_float2((o[nt][2] + p48_1 * vv[nt].x) * linv1,
                                (o[nt][3] + p48_1 * vv[nt].y) * linv1);
        }
    }
}

extern "C" void kernel_launch(void* const* d_in, const int* in_sizes, int n_in,
                              void* d_out, int out_size)
{
    const float* q = (const float*)d_in[0];
    const float* k = (const float*)d_in[1];
    const float* v = (const float*)d_in[2];
    float* out = (float*)d_out;

    const int bh = in_sizes[0] / (kNQ * kD);   // 4096
    attn49_v12<<<bh, 128>>>(q, k, v, out);
}

// round 13
// speedup vs baseline: 1.4390x; 1.0011x over previous
#include <cuda_runtime.h>
#include <cuda_fp16.h>
#include <math_constants.h>
#include <cstdint>

// Attention B=256,H=16,Nq=Nk=49,D=64 fp32. One CTA (128 thr, 4 warps) per (b,h).
// R13: fp16 asymmetric 2-term tensor-core GEMMs (fp32 accum):
//   phase1  S = Q_h . (K_h + K_l)   (Q single fp16, K split hi/lo)
//   phase2  O = P_h . (V_h + V_l)   (P single fp16, V split hi/lo)
// Key 48 folded out of phase-2 MMA as scalar fp32 rank-1 update (R12).
// Smem 27.9KB, launch_bounds(128,8), one barrier, log2-domain softmax.

namespace {
constexpr int kNQ = 49, kNK = 49, kD = 64;
constexpr int kP  = 72;                     // fp16 pitch (144B = 9*16)
constexpr float kQscale = 0.125f * 1.4426950408889634f;  // scale * log2(e)
constexpr float kEps    = 1e-9f;
constexpr int kROWB = 144;
constexpr int OFF_KH = 0;
constexpr int OFF_KL = 49 * kROWB;              // 7056
constexpr int OFF_VH = 2 * 49 * kROWB;          // 14112
constexpr int OFF_VL = OFF_VH + 48 * kROWB;     // 21024
constexpr int SMEM_BYTES = OFF_VL + 48 * kROWB; // 27936
}

__device__ __forceinline__ uint32_t cvta_s(const void* p) {
    return (uint32_t)__cvta_generic_to_shared(p);
}
__device__ __forceinline__ void ldsm4(uint32_t& r0, uint32_t& r1, uint32_t& r2, uint32_t& r3, uint32_t a) {
    asm volatile("ldmatrix.sync.aligned.m8n8.x4.shared.b16 {%0,%1,%2,%3}, [%4];\n"
                 : "=r"(r0), "=r"(r1), "=r"(r2), "=r"(r3) : "r"(a));
}
__device__ __forceinline__ void ldsm2(uint32_t& r0, uint32_t& r1, uint32_t a) {
    asm volatile("ldmatrix.sync.aligned.m8n8.x2.shared.b16 {%0,%1}, [%2];\n"
                 : "=r"(r0), "=r"(r1) : "r"(a));
}
__device__ __forceinline__ void ldsm4t(uint32_t& r0, uint32_t& r1, uint32_t& r2, uint32_t& r3, uint32_t a) {
    asm volatile("ldmatrix.sync.aligned.m8n8.x4.trans.shared.b16 {%0,%1,%2,%3}, [%4];\n"
                 : "=r"(r0), "=r"(r1), "=r"(r2), "=r"(r3) : "r"(a));
}
__device__ __forceinline__ void mma16816(float* c,
                                         uint32_t a0, uint32_t a1, uint32_t a2, uint32_t a3,
                                         uint32_t b0, uint32_t b1) {
    asm volatile("mma.sync.aligned.m16n8k16.row.col.f32.f16.f16.f32 "
                 "{%0,%1,%2,%3}, {%4,%5,%6,%7}, {%8,%9}, {%0,%1,%2,%3};\n"
                 : "+f"(c[0]), "+f"(c[1]), "+f"(c[2]), "+f"(c[3])
                 : "r"(a0), "r"(a1), "r"(a2), "r"(a3), "r"(b0), "r"(b1));
}
__device__ __forceinline__ uint32_t packh2(float lo, float hi) {
    uint32_t r;
    asm("cvt.rn.f16x2.f32 %0, %1, %2;" : "=r"(r) : "f"(hi), "f"(lo));
    return r;
}
__device__ __forceinline__ float2 unpackh2(uint32_t h) {
    const __half2 x = *reinterpret_cast<const __half2*>(&h);
    return __half22float2(x);
}

__global__ __launch_bounds__(128, 8)
void attn49_v13(const float* __restrict__ gq,
                const float* __restrict__ gk,
                const float* __restrict__ gv,
                float* __restrict__ gout)
{
    __shared__ __align__(16) char sraw[SMEM_BYTES];

    const int tid  = threadIdx.x;
    const int w    = tid >> 5;
    const int lane = tid & 31;
    const int g    = lane >> 3;
    const int lr   = lane & 7;

    const size_t base = (size_t)blockIdx.x * (kNQ * kD);
    const float2* Q2 = (const float2*)(gq + base);
    const float4* K4 = (const float4*)(gk + base);
    const float4* V4 = (const float4*)(gv + base);
    float* O = gout + base;

    const int qtb = w * 16;
    const int q0 = qtb + (lane >> 2);
    const int q1 = q0 + 8;
    const bool p0 = q0 < kNQ;
    const bool p1 = q1 < kNQ;
    const int cq = 2 * (lane & 3);

    // ---- K (rows 0-48) and V (rows 0-47) load + fp16 hi/lo split ----
    for (int idx = tid; idx < 49 * 16; idx += 128) {
        const int r = idx >> 4, c4 = idx & 15;
        const float4 k = K4[idx];
        {
            const uint32_t h01 = packh2(k.x, k.y);
            const uint32_t h23 = packh2(k.z, k.w);
            const float2 f01 = unpackh2(h01), f23 = unpackh2(h23);
            *(uint2*)(sraw + OFF_KH + r * kROWB + c4 * 8) = make_uint2(h01, h23);
            *(uint2*)(sraw + OFF_KL + r * kROWB + c4 * 8) =
                make_uint2(packh2(k.x - f01.x, k.y - f01.y),
                           packh2(k.z - f23.x, k.w - f23.y));
        }
        if (r < 48) {
            const float4 v = V4[idx];
            const uint32_t h01 = packh2(v.x, v.y);
            const uint32_t h23 = packh2(v.z, v.w);
            const float2 f01 = unpackh2(h01), f23 = unpackh2(h23);
            *(uint2*)(sraw + OFF_VH + r * kROWB + c4 * 8) = make_uint2(h01, h23);
            *(uint2*)(sraw + OFF_VL + r * kROWB + c4 * 8) =
                make_uint2(packh2(v.x - f01.x, v.y - f01.y),
                           packh2(v.z - f23.x, v.w - f23.y));
        }
    }
    __syncthreads();   // the ONLY barrier

    // ---- Phase 1: S[16q][56k] = Q_h . (K_h + K_l); tile 48-55 via ldsm.x2 ----
    float acc[7][4];
    #pragma unroll
    for (int i = 0; i < 7; i++)
        #pragma unroll
        for (int j = 0; j < 4; j++) acc[i][j] = 0.0f;
    {
        const uint32_t aKh = cvta_s(sraw + OFF_KH);
        const uint32_t aKl = cvta_s(sraw + OFF_KL);
        const int ro = lr + ((g & 1) << 3);
        const int co = (g >> 1) << 3;
        #pragma unroll
        for (int kc = 0; kc < 4; kc++) {
            // Q chunk (scaled by 1/8*log2e), single fp16
            uint32_t ah[4];
            {
                const int cb = kc * 8 + (lane & 3);
                float2 x0 = p0 ? Q2[q0 * 32 + cb]     : make_float2(0.f, 0.f);
                float2 x1 = p1 ? Q2[q1 * 32 + cb]     : make_float2(0.f, 0.f);
                float2 x2 = p0 ? Q2[q0 * 32 + cb + 4] : make_float2(0.f, 0.f);
                float2 x3 = p1 ? Q2[q1 * 32 + cb + 4] : make_float2(0.f, 0.f);
                ah[0] = packh2(x0.x * kQscale, x0.y * kQscale);
                ah[1] = packh2(x1.x * kQscale, x1.y * kQscale);
                ah[2] = packh2(x2.x * kQscale, x2.y * kQscale);
                ah[3] = packh2(x3.x * kQscale, x3.y * kQscale);
            }
            const int d = kc * 16;
            // pair 0: key rows 0-31 (acc0..3), 4 chains x 2 terms
            {
                const int b0 = ro * kP + d + co;
                const int b1 = (16 + ro) * kP + d + co;
                uint32_t xh0, xh1, xh2, xh3, xl0, xl1, xl2, xl3;
                uint32_t yh0, yh1, yh2, yh3, yl0, yl1, yl2, yl3;
                ldsm4(xh0, xh1, xh2, xh3, aKh + b0 * 2);
                ldsm4(yh0, yh1, yh2, yh3, aKh + b1 * 2);
                ldsm4(xl0, xl1, xl2, xl3, aKl + b0 * 2);
                ldsm4(yl0, yl1, yl2, yl3, aKl + b1 * 2);
                mma16816(acc[0], ah[0], ah[1], ah[2], ah[3], xh0, xh2);
                mma16816(acc[1], ah[0], ah[1], ah[2], ah[3], xh1, xh3);
                mma16816(acc[2], ah[0], ah[1], ah[2], ah[3], yh0, yh2);
                mma16816(acc[3], ah[0], ah[1], ah[2], ah[3], yh1, yh3);
                mma16816(acc[0], ah[0], ah[1], ah[2], ah[3], xl0, xl2);
                mma16816(acc[1], ah[0], ah[1], ah[2], ah[3], xl1, xl3);
                mma16816(acc[2], ah[0], ah[1], ah[2], ah[3], yl0, yl2);
                mma16816(acc[3], ah[0], ah[1], ah[2], ah[3], yl1, yl3);
            }
            // pair 1: key rows 32-47 (acc4,5) + rows 48-55 (acc6, x2)
            {
                const int b2 = (32 + ro) * kP + d + co;
                const int b3 = (48 + lr) * kP + d + ((g & 1) << 3);   // x2: 7-row spill, masked
                uint32_t zh0, zh1, zh2, zh3, zl0, zl1, zl2, zl3;
                uint32_t wh0, wh1, wl0, wl1;
                ldsm4(zh0, zh1, zh2, zh3, aKh + b2 * 2);
                ldsm2(wh0, wh1, aKh + b3 * 2);
                ldsm4(zl0, zl1, zl2, zl3, aKl + b2 * 2);
                ldsm2(wl0, wl1, aKl + b3 * 2);
                mma16816(acc[4], ah[0], ah[1], ah[2], ah[3], zh0, zh2);
                mma16816(acc[5], ah[0], ah[1], ah[2], ah[3], zh1, zh3);
                mma16816(acc[6], ah[0], ah[1], ah[2], ah[3], wh0, wh1);
                mma16816(acc[4], ah[0], ah[1], ah[2], ah[3], zl0, zl2);
                mma16816(acc[5], ah[0], ah[1], ah[2], ah[3], zl1, zl3);
                mma16816(acc[6], ah[0], ah[1], ah[2], ah[3], wl0, wl1);
            }
        }
    }

    // ---- Register softmax, log2 domain ----
    float m0 = -CUDART_INF_F, m1 = -CUDART_INF_F;
    #pragma unroll
    for (int nt = 0; nt < 7; nt++) {
        const int c0 = nt * 8 + cq;
        const bool v0 = (c0 < kNK), v1 = (c0 + 1 < kNK);
        m0 = fmaxf(m0, v0 ? acc[nt][0] : -CUDART_INF_F);
        m0 = fmaxf(m0, v1 ? acc[nt][1] : -CUDART_INF_F);
        m1 = fmaxf(m1, v0 ? acc[nt][2] : -CUDART_INF_F);
        m1 = fmaxf(m1, v1 ? acc[nt][3] : -CUDART_INF_F);
    }
    m0 = fmaxf(m0, __shfl_xor_sync(0xffffffffu, m0, 1));
    m0 = fmaxf(m0, __shfl_xor_sync(0xffffffffu, m0, 2));
    m1 = fmaxf(m1, __shfl_xor_sync(0xffffffffu, m1, 1));
    m1 = fmaxf(m1, __shfl_xor_sync(0xffffffffu, m1, 2));

    float l0 = 0.0f, l1 = 0.0f;
    #pragma unroll
    for (int nt = 0; nt < 7; nt++) {
        const int c0 = nt * 8 + cq;
        const bool v0 = (c0 < kNK), v1 = (c0 + 1 < kNK);
        const float e0 = v0 ? exp2f(acc[nt][0] - m0) : 0.0f;
        const float e1 = v1 ? exp2f(acc[nt][1] - m0) : 0.0f;
        const float e2 = v0 ? exp2f(acc[nt][2] - m1) : 0.0f;
        const float e3 = v1 ? exp2f(acc[nt][3] - m1) : 0.0f;
        acc[nt][0] = e0; acc[nt][1] = e1; acc[nt][2] = e2; acc[nt][3] = e3;
        l0 += e0 + e1; l1 += e2 + e3;
    }
    l0 += __shfl_xor_sync(0xffffffffu, l0, 1);
    l0 += __shfl_xor_sync(0xffffffffu, l0, 2);
    l1 += __shfl_xor_sync(0xffffffffu, l1, 1);
    l1 += __shfl_xor_sync(0xffffffffu, l1, 2);
    const float linv0 = 1.0f / (l0 + kEps);
    const float linv1 = 1.0f / (l1 + kEps);

    // p48 = exp value for key 48 (quad leader holds col 48 = nt6,cq0), fp32
    const float p48_0 = __shfl_sync(0xffffffffu, acc[6][0], lane & ~3);
    const float p48_1 = __shfl_sync(0xffffffffu, acc[6][2], lane & ~3);

    // ---- Repack P (cols 0-47) as single-fp16 A-fragments ----
    uint32_t aP[3][4];
    #pragma unroll
    for (int kc = 0; kc < 3; kc++) {
        #pragma unroll
        for (int t = 0; t < 2; t++) {
            aP[kc][2 * t]     = packh2(acc[2 * kc + t][0], acc[2 * kc + t][1]);
            aP[kc][2 * t + 1] = packh2(acc[2 * kc + t][2], acc[2 * kc + t][3]);
        }
    }

    // ---- Phase 2: O = P_h.(V_h+V_l) over k 0-47 + p48*V[48] (scalar fp32) ----
    const uint32_t aVh = cvta_s(sraw + OFF_VH);
    const uint32_t aVl = cvta_s(sraw + OFF_VL);
    const float2* V48 = (const float2*)(gv + base + 48 * kD);
    #pragma unroll
    for (int half = 0; half < 2; half++) {
        const int db = half * 32;
        float2 vv[4];
        #pragma unroll
        for (int nt = 0; nt < 4; nt++)
            vv[nt] = V48[(db >> 1) + nt * 4 + (cq >> 1)];

        float o[4][4];
        #pragma unroll
        for (int i = 0; i < 4; i++)
            #pragma unroll
            for (int j = 0; j < 4; j++) o[i][j] = 0.0f;

        #pragma unroll
        for (int kc = 0; kc < 3; kc++) {
            const int kk = kc * 16;
            const int bo0 = (kk + ((g >> 1) << 3) + lr) * kP + db      + ((g & 1) << 3);
            const int bo1 = (kk + ((g >> 1) << 3) + lr) * kP + db + 16 + ((g & 1) << 3);
            uint32_t xh0, xh1, xh2, xh3, xl0, xl1, xl2, xl3;
            uint32_t yh0, yh1, yh2, yh3, yl0, yl1, yl2, yl3;
            ldsm4t(xh0, xh1, xh2, xh3, aVh + bo0 * 2);
            ldsm4t(yh0, yh1, yh2, yh3, aVh + bo1 * 2);
            ldsm4t(xl0, xl1, xl2, xl3, aVl + bo0 * 2);
            ldsm4t(yl0, yl1, yl2, yl3, aVl + bo1 * 2);
            mma16816(o[0], aP[kc][0], aP[kc][1], aP[kc][2], aP[kc][3], xh0, xh2);
            mma16816(o[1], aP[kc][0], aP[kc][1], aP[kc][2], aP[kc][3], xh1, xh3);
            mma16816(o[2], aP[kc][0], aP[kc][1], aP[kc][2], aP[kc][3], yh0, yh2);
            mma16816(o[3], aP[kc][0], aP[kc][1], aP[kc][2], aP[kc][3], yh1, yh3);
            mma16816(o[0], aP[kc][0], aP[kc][1], aP[kc][2], aP[kc][3], xl0, xl2);
            mma16816(o[1], aP[kc][0], aP[kc][1], aP[kc][2], aP[kc][3], xl1, xl3);
            mma16816(o[2], aP[kc][0], aP[kc][1], aP[kc][2], aP[kc][3], yl0, yl2);
            mma16816(o[3], aP[kc][0], aP[kc][1], aP[kc][2], aP[kc][3], yl1, yl3);
        }

        #pragma unroll
        for (int nt = 0; nt < 4; nt++) {
            const int d = db + nt * 8 + cq;
            if (p0)
                *(float2*)(O + q0 * kD + d) =
                    make_float2((o[nt][0] + p48_0 * vv[nt].x) * linv0,
                                (o[nt][1] + p48_0 * vv[nt].y) * linv0);
            if (p1)
                *(float2*)(O + q1 * kD + d) =
                    make_float2((o[nt][2] + p48_1 * vv[nt].x) * linv1,
                                (o[nt][3] + p48_1 * vv[nt].y) * linv1);
        }
    }
}

extern "C" void kernel_launch(void* const* d_in, const int* in_sizes, int n_in,
                              void* d_out, int out_size)
{
    const float* q = (const float*)d_in[0];
    const float* k = (const float*)d_in[1];
    const float* v = (const float*)d_in[2];
    float* out = (float*)d_out;

    const int bh = in_sizes[0] / (kNQ * kD);   // 4096
    attn49_v13<<<bh, 128>>>(q, k, v, out);
}

// round 14
// speedup vs baseline: 1.6652x; 1.1572x over previous
#include <cuda_runtime.h>
#include <cuda_fp16.h>
#include <math_constants.h>
#include <cstdint>

// Attention B=256,H=16,Nq=Nk=49,D=64 fp32. One CTA (128 thr, 4 warps) per (b,h).
// R14: fp16 tensor-core GEMMs (fp32 accum), L1-wavefront-minimized:
//   phase1  S[:,0:48] = Q_h . (K_h + K_l)   (K 2-term, rows 0-47 only)
//   s48 scalar fp32 (exact): Q regs x K[48] via FMA + quad shuffles
//   phase2  O = P_h . V_h (single term) over k 0-47 + p48*V[48] scalar fp32
// 48-row smem arrays (no LDSM spill), 20.3KB smem, launch_bounds(128,9).
// One barrier, log2-domain softmax, no masking (cols 0-47 all valid).

namespace {
constexpr int kNQ = 49, kNK = 49, kD = 64;
constexpr int kP  = 72;                     // fp16 pitch (144B = 9*16)
constexpr float kQscale = 0.125f * 1.4426950408889634f;  // scale * log2(e)
constexpr float kEps    = 1e-9f;
constexpr int kROWB = 144;
constexpr int OFF_KH = 0;
constexpr int OFF_KL = 48 * kROWB;              // 6912
constexpr int OFF_VH = 2 * 48 * kROWB;          // 13824
constexpr int SMEM_BYTES = OFF_VH + 48 * kROWB; // 20736
}

__device__ __forceinline__ uint32_t cvta_s(const void* p) {
    return (uint32_t)__cvta_generic_to_shared(p);
}
__device__ __forceinline__ void ldsm4(uint32_t& r0, uint32_t& r1, uint32_t& r2, uint32_t& r3, uint32_t a) {
    asm volatile("ldmatrix.sync.aligned.m8n8.x4.shared.b16 {%0,%1,%2,%3}, [%4];\n"
                 : "=r"(r0), "=r"(r1), "=r"(r2), "=r"(r3) : "r"(a));
}
__device__ __forceinline__ void ldsm4t(uint32_t& r0, uint32_t& r1, uint32_t& r2, uint32_t& r3, uint32_t a) {
    asm volatile("ldmatrix.sync.aligned.m8n8.x4.trans.shared.b16 {%0,%1,%2,%3}, [%4];\n"
                 : "=r"(r0), "=r"(r1), "=r"(r2), "=r"(r3) : "r"(a));
}
__device__ __forceinline__ void mma16816(float* c,
                                         uint32_t a0, uint32_t a1, uint32_t a2, uint32_t a3,
                                         uint32_t b0, uint32_t b1) {
    asm volatile("mma.sync.aligned.m16n8k16.row.col.f32.f16.f16.f32 "
                 "{%0,%1,%2,%3}, {%4,%5,%6,%7}, {%8,%9}, {%0,%1,%2,%3};\n"
                 : "+f"(c[0]), "+f"(c[1]), "+f"(c[2]), "+f"(c[3])
                 : "r"(a0), "r"(a1), "r"(a2), "r"(a3), "r"(b0), "r"(b1));
}
__device__ __forceinline__ uint32_t packh2(float lo, float hi) {
    uint32_t r;
    asm("cvt.rn.f16x2.f32 %0, %1, %2;" : "=r"(r) : "f"(hi), "f"(lo));
    return r;
}
__device__ __forceinline__ float2 unpackh2(uint32_t h) {
    const __half2 x = *reinterpret_cast<const __half2*>(&h);
    return __half22float2(x);
}

__global__ __launch_bounds__(128, 9)
void attn49_v14(const float* __restrict__ gq,
                const float* __restrict__ gk,
                const float* __restrict__ gv,
                float* __restrict__ gout)
{
    __shared__ __align__(16) char sraw[SMEM_BYTES];

    const int tid  = threadIdx.x;
    const int w    = tid >> 5;
    const int lane = tid & 31;
    const int g    = lane >> 3;
    const int lr   = lane & 7;

    const size_t base = (size_t)blockIdx.x * (kNQ * kD);
    const float2* Q2  = (const float2*)(gq + base);
    const float4* K4  = (const float4*)(gk + base);
    const float4* V4  = (const float4*)(gv + base);
    const float2* K48 = (const float2*)(gk + base + 48 * kD);
    const float2* V48 = (const float2*)(gv + base + 48 * kD);
    float* O = gout + base;

    const int qtb = w * 16;
    const int q0 = qtb + (lane >> 2);
    const int q1 = q0 + 8;
    const bool p0 = q0 < kNQ;
    const bool p1 = q1 < kNQ;
    const int cq = 2 * (lane & 3);

    // ---- K rows 0-47 (hi/lo split) and V rows 0-47 (hi only) -> smem ----
    for (int idx = tid; idx < 48 * 16; idx += 128) {
        const int r = idx >> 4, c4 = idx & 15;
        const float4 k = K4[idx];
        const float4 v = V4[idx];
        const uint32_t kh01 = packh2(k.x, k.y);
        const uint32_t kh23 = packh2(k.z, k.w);
        const float2 f01 = unpackh2(kh01), f23 = unpackh2(kh23);
        *(uint2*)(sraw + OFF_KH + r * kROWB + c4 * 8) = make_uint2(kh01, kh23);
        *(uint2*)(sraw + OFF_KL + r * kROWB + c4 * 8) =
            make_uint2(packh2(k.x - f01.x, k.y - f01.y),
                       packh2(k.z - f23.x, k.w - f23.y));
        *(uint2*)(sraw + OFF_VH + r * kROWB + c4 * 8) =
            make_uint2(packh2(v.x, v.y), packh2(v.z, v.w));
    }
    __syncthreads();   // the ONLY barrier

    // ---- Phase 1: S[16q][48k] = Q_h.(K_h+K_l); s48 scalar fp32 alongside ----
    float acc[6][4];
    #pragma unroll
    for (int i = 0; i < 6; i++)
        #pragma unroll
        for (int j = 0; j < 4; j++) acc[i][j] = 0.0f;
    float s48_0 = 0.0f, s48_1 = 0.0f;
    {
        const uint32_t aKh = cvta_s(sraw + OFF_KH);
        const uint32_t aKl = cvta_s(sraw + OFF_KL);
        const int ro = lr + ((g & 1) << 3);
        const int co = (g >> 1) << 3;
        #pragma unroll
        for (int kc = 0; kc < 4; kc++) {
            // Q chunk (scaled by 1/8*log2e): fp32 for s48, fp16 for MMA A
            uint32_t ah[4];
            {
                const int cb = kc * 8 + (lane & 3);
                float2 x0 = p0 ? Q2[q0 * 32 + cb]     : make_float2(0.f, 0.f);
                float2 x1 = p1 ? Q2[q1 * 32 + cb]     : make_float2(0.f, 0.f);
                float2 x2 = p0 ? Q2[q0 * 32 + cb + 4] : make_float2(0.f, 0.f);
                float2 x3 = p1 ? Q2[q1 * 32 + cb + 4] : make_float2(0.f, 0.f);
                x0.x *= kQscale; x0.y *= kQscale; x1.x *= kQscale; x1.y *= kQscale;
                x2.x *= kQscale; x2.y *= kQscale; x3.x *= kQscale; x3.y *= kQscale;
                ah[0] = packh2(x0.x, x0.y);
                ah[1] = packh2(x1.x, x1.y);
                ah[2] = packh2(x2.x, x2.y);
                ah[3] = packh2(x3.x, x3.y);
                // s48 partial: fp32 exact, same scaled values
                const float2 ka = K48[cb];
                const float2 kb = K48[cb + 4];
                s48_0 = fmaf(x0.x, ka.x, fmaf(x0.y, ka.y,
                        fmaf(x2.x, kb.x, fmaf(x2.y, kb.y, s48_0))));
                s48_1 = fmaf(x1.x, ka.x, fmaf(x1.y, ka.y,
                        fmaf(x3.x, kb.x, fmaf(x3.y, kb.y, s48_1))));
            }
            const int d = kc * 16;
            // key rows 0-31 (acc0..3), 4 chains x 2 terms
            {
                const int b0 = ro * kP + d + co;
                const int b1 = (16 + ro) * kP + d + co;
                uint32_t xh0, xh1, xh2, xh3, xl0, xl1, xl2, xl3;
                uint32_t yh0, yh1, yh2, yh3, yl0, yl1, yl2, yl3;
                ldsm4(xh0, xh1, xh2, xh3, aKh + b0 * 2);
                ldsm4(yh0, yh1, yh2, yh3, aKh + b1 * 2);
                ldsm4(xl0, xl1, xl2, xl3, aKl + b0 * 2);
                ldsm4(yl0, yl1, yl2, yl3, aKl + b1 * 2);
                mma16816(acc[0], ah[0], ah[1], ah[2], ah[3], xh0, xh2);
                mma16816(acc[1], ah[0], ah[1], ah[2], ah[3], xh1, xh3);
                mma16816(acc[2], ah[0], ah[1], ah[2], ah[3], yh0, yh2);
                mma16816(acc[3], ah[0], ah[1], ah[2], ah[3], yh1, yh3);
                mma16816(acc[0], ah[0], ah[1], ah[2], ah[3], xl0, xl2);
                mma16816(acc[1], ah[0], ah[1], ah[2], ah[3], xl1, xl3);
                mma16816(acc[2], ah[0], ah[1], ah[2], ah[3], yl0, yl2);
                mma16816(acc[3], ah[0], ah[1], ah[2], ah[3], yl1, yl3);
            }
            // key rows 32-47 (acc4,5), 2 chains x 2 terms
            {
                const int b2 = (32 + ro) * kP + d + co;
                uint32_t zh0, zh1, zh2, zh3, zl0, zl1, zl2, zl3;
                ldsm4(zh0, zh1, zh2, zh3, aKh + b2 * 2);
                ldsm4(zl0, zl1, zl2, zl3, aKl + b2 * 2);
                mma16816(acc[4], ah[0], ah[1], ah[2], ah[3], zh0, zh2);
                mma16816(acc[5], ah[0], ah[1], ah[2], ah[3], zh1, zh3);
                mma16816(acc[4], ah[0], ah[1], ah[2], ah[3], zl0, zl2);
                mma16816(acc[5], ah[0], ah[1], ah[2], ah[3], zl1, zl3);
            }
        }
        // complete s48 across the quad (cols partitioned over 4 lanes)
        s48_0 += __shfl_xor_sync(0xffffffffu, s48_0, 1);
        s48_0 += __shfl_xor_sync(0xffffffffu, s48_0, 2);
        s48_1 += __shfl_xor_sync(0xffffffffu, s48_1, 1);
        s48_1 += __shfl_xor_sync(0xffffffffu, s48_1, 2);
    }

    // ---- Register softmax, log2 domain (cols 0-47 all valid + scalar s48) ----
    float m0 = s48_0, m1 = s48_1;
    #pragma unroll
    for (int nt = 0; nt < 6; nt++) {
        m0 = fmaxf(m0, fmaxf(acc[nt][0], acc[nt][1]));
        m1 = fmaxf(m1, fmaxf(acc[nt][2], acc[nt][3]));
    }
    m0 = fmaxf(m0, __shfl_xor_sync(0xffffffffu, m0, 1));
    m0 = fmaxf(m0, __shfl_xor_sync(0xffffffffu, m0, 2));
    m1 = fmaxf(m1, __shfl_xor_sync(0xffffffffu, m1, 1));
    m1 = fmaxf(m1, __shfl_xor_sync(0xffffffffu, m1, 2));

    float l0 = 0.0f, l1 = 0.0f;
    #pragma unroll
    for (int nt = 0; nt < 6; nt++) {
        const float e0 = exp2f(acc[nt][0] - m0);
        const float e1 = exp2f(acc[nt][1] - m0);
        const float e2 = exp2f(acc[nt][2] - m1);
        const float e3 = exp2f(acc[nt][3] - m1);
        acc[nt][0] = e0; acc[nt][1] = e1; acc[nt][2] = e2; acc[nt][3] = e3;
        l0 += e0 + e1; l1 += e2 + e3;
    }
    l0 += __shfl_xor_sync(0xffffffffu, l0, 1);
    l0 += __shfl_xor_sync(0xffffffffu, l0, 2);
    l1 += __shfl_xor_sync(0xffffffffu, l1, 1);
    l1 += __shfl_xor_sync(0xffffffffu, l1, 2);

    const float p48_0 = exp2f(s48_0 - m0);   // same value across quad
    const float p48_1 = exp2f(s48_1 - m1);
    const float linv0 = 1.0f / (l0 + p48_0 + kEps);
    const float linv1 = 1.0f / (l1 + p48_1 + kEps);

    // ---- Repack P (cols 0-47) as single-fp16 A-fragments ----
    uint32_t aP[3][4];
    #pragma unroll
    for (int kc = 0; kc < 3; kc++) {
        #pragma unroll
        for (int t = 0; t < 2; t++) {
            aP[kc][2 * t]     = packh2(acc[2 * kc + t][0], acc[2 * kc + t][1]);
            aP[kc][2 * t + 1] = packh2(acc[2 * kc + t][2], acc[2 * kc + t][3]);
        }
    }

    // ---- Phase 2: O = P_h.V_h over k 0-47 + p48*V[48] (scalar fp32) ----
    const uint32_t aVh = cvta_s(sraw + OFF_VH);
    #pragma unroll
    for (int half = 0; half < 2; half++) {
        const int db = half * 32;
        float2 vv[4];
        #pragma unroll
        for (int nt = 0; nt < 4; nt++)
            vv[nt] = V48[(db >> 1) + nt * 4 + (cq >> 1)];

        float o[4][4];
        #pragma unroll
        for (int i = 0; i < 4; i++)
            #pragma unroll
            for (int j = 0; j < 4; j++) o[i][j] = 0.0f;

        #pragma unroll
        for (int kc = 0; kc < 3; kc++) {
            const int kk = kc * 16;
            const int bo0 = (kk + ((g >> 1) << 3) + lr) * kP + db      + ((g & 1) << 3);
            const int bo1 = (kk + ((g >> 1) << 3) + lr) * kP + db + 16 + ((g & 1) << 3);
            uint32_t xh0, xh1, xh2, xh3;
            uint32_t yh0, yh1, yh2, yh3;
            ldsm4t(xh0, xh1, xh2, xh3, aVh + bo0 * 2);
            ldsm4t(yh0, yh1, yh2, yh3, aVh + bo1 * 2);
            mma16816(o[0], aP[kc][0], aP[kc][1], aP[kc][2], aP[kc][3], xh0, xh2);
            mma16816(o[1], aP[kc][0], aP[kc][1], aP[kc][2], aP[kc][3], xh1, xh3);
            mma16816(o[2], aP[kc][0], aP[kc][1], aP[kc][2], aP[kc][3], yh0, yh2);
            mma16816(o[3], aP[kc][0], aP[kc][1], aP[kc][2], aP[kc][3], yh1, yh3);
        }

        #pragma unroll
        for (int nt = 0; nt < 4; nt++) {
            const int d = db + nt * 8 + cq;
            if (p0)
                *(float2*)(O + q0 * kD + d) =
                    make_float2((o[nt][0] + p48_0 * vv[nt].x) * linv0,
                                (o[nt][1] + p48_0 * vv[nt].y) * linv0);
            if (p1)
                *(float2*)(O + q1 * kD + d) =
                    make_float2((o[nt][2] + p48_1 * vv[nt].x) * linv1,
                                (o[nt][3] + p48_1 * vv[nt].y) * linv1);
        }
    }
}

extern "C" void kernel_launch(void* const* d_in, const int* in_sizes, int n_in,
                              void* d_out, int out_size)
{
    const float* q = (const float*)d_in[0];
    const float* k = (const float*)d_in[1];
    const float* v = (const float*)d_in[2];
    float* out = (float*)d_out;

    const int bh = in_sizes[0] / (kNQ * kD);   // 4096
    attn49_v14<<<bh, 128>>>(q, k, v, out);
}